// round 8
// baseline (speedup 1.0000x reference)
#include <cuda_runtime.h>
#include <math.h>

// Problem constants
#define BDIM 16
#define CDIM 512
#define NDIM 1024
#define NHEADS 8
#define DHEAD 64
#define QSCALE 0.125f

// Scratch: q (pre-scaled), k' (= k + cp_tab), v. Layout [B][C][N] fp32.
__device__ float g_q[BDIM * CDIM * NDIM];
__device__ float g_k[BDIM * CDIM * NDIM];
__device__ float g_v[BDIM * CDIM * NDIM];

// ---------------------------------------------------------------------------
// Kernel 1: fused QKV projection, 128(o) x 128(n) tile, 256 threads, 8x8/thread.
// (unchanged from R4 — sustains ~2.5 warp-FFMA/cyc/SM)
// ---------------------------------------------------------------------------
__global__ __launch_bounds__(256) void qkv_gemm_kernel(
    const float* __restrict__ x,
    const float* __restrict__ Wq, const float* __restrict__ bq,
    const float* __restrict__ Wk, const float* __restrict__ bk,
    const float* __restrict__ Wv, const float* __restrict__ bv,
    const float* __restrict__ rel_h, const float* __restrict__ rel_w)
{
    const int mat = blockIdx.z >> 4;   // 0=q, 1=k, 2=v
    const int b   = blockIdx.z & 15;

    const float* __restrict__ W    = (mat == 0) ? Wq : (mat == 1) ? Wk : Wv;
    const float* __restrict__ bias = (mat == 0) ? bq : (mat == 1) ? bk : bv;
    float* __restrict__ out        = (mat == 0) ? g_q : (mat == 1) ? g_k : g_v;

    const int o0 = blockIdx.y * 128;
    const int n0 = blockIdx.x * 128;

    __shared__ float Ws[16 * 132];   // [k][o] transposed, padded
    __shared__ float Xs[16 * 132];   // [k][n], padded

    const int tid = threadIdx.x;
    const int tr  = tid >> 4;        // 0..15 -> o groups
    const int tc  = tid & 15;        // 0..15 -> n groups

    float acc[8][8];
#pragma unroll
    for (int r = 0; r < 8; r++)
#pragma unroll
        for (int c = 0; c < 8; c++) acc[r][c] = 0.f;

    const float* __restrict__ xb = x + (size_t)b * CDIM * NDIM;

    const int wrow = tid >> 1;            // 0..127 (o row)
    const int wk   = (tid & 1) * 8;       // 0 or 8 (k offset)
    const int xrow = tid >> 4;            // 0..15  (k row)
    const int xcol = (tid & 15) * 8;      // n offset

    float4 w0 = *(const float4*)&W[(size_t)(o0 + wrow) * CDIM + wk];
    float4 w1 = *(const float4*)&W[(size_t)(o0 + wrow) * CDIM + wk + 4];
    float4 x0 = *(const float4*)&xb[(size_t)xrow * NDIM + n0 + xcol];
    float4 x1 = *(const float4*)&xb[(size_t)xrow * NDIM + n0 + xcol + 4];

    for (int k0 = 0; k0 < CDIM; k0 += 16) {
        __syncthreads();
        Ws[(wk + 0) * 132 + wrow] = w0.x;
        Ws[(wk + 1) * 132 + wrow] = w0.y;
        Ws[(wk + 2) * 132 + wrow] = w0.z;
        Ws[(wk + 3) * 132 + wrow] = w0.w;
        Ws[(wk + 4) * 132 + wrow] = w1.x;
        Ws[(wk + 5) * 132 + wrow] = w1.y;
        Ws[(wk + 6) * 132 + wrow] = w1.z;
        Ws[(wk + 7) * 132 + wrow] = w1.w;
        *(float4*)&Xs[xrow * 132 + xcol]     = x0;
        *(float4*)&Xs[xrow * 132 + xcol + 4] = x1;
        __syncthreads();

        if (k0 + 16 < CDIM) {
            w0 = *(const float4*)&W[(size_t)(o0 + wrow) * CDIM + k0 + 16 + wk];
            w1 = *(const float4*)&W[(size_t)(o0 + wrow) * CDIM + k0 + 16 + wk + 4];
            x0 = *(const float4*)&xb[(size_t)(k0 + 16 + xrow) * NDIM + n0 + xcol];
            x1 = *(const float4*)&xb[(size_t)(k0 + 16 + xrow) * NDIM + n0 + xcol + 4];
        }

#pragma unroll 8
        for (int kk = 0; kk < 16; kk++) {
            float4 a0 = *(const float4*)&Ws[kk * 132 + 4 * tr];
            float4 a1 = *(const float4*)&Ws[kk * 132 + 64 + 4 * tr];
            float4 b0 = *(const float4*)&Xs[kk * 132 + 4 * tc];
            float4 b1 = *(const float4*)&Xs[kk * 132 + 64 + 4 * tc];
            float a[8] = {a0.x, a0.y, a0.z, a0.w, a1.x, a1.y, a1.z, a1.w};
            float bb[8] = {b0.x, b0.y, b0.z, b0.w, b1.x, b1.y, b1.z, b1.w};
#pragma unroll
            for (int r = 0; r < 8; r++)
#pragma unroll
                for (int c = 0; c < 8; c++)
                    acc[r][c] += a[r] * bb[c];
        }
    }

    const size_t obase = (size_t)b * CDIM * NDIM;
#pragma unroll
    for (int r = 0; r < 8; r++) {
        const int o  = o0 + ((r < 4) ? (4 * tr + r) : (64 + 4 * tr + (r - 4)));
        const float bi = bias[o];
        const int dd = o & 63;
#pragma unroll
        for (int g = 0; g < 2; g++) {
            const int nb = n0 + (g ? (64 + 4 * tc) : (4 * tc));
            float vals[4];
#pragma unroll
            for (int c = 0; c < 4; c++) {
                const int n = nb + c;
                float val = acc[r][g * 4 + c] + bi;
                if (mat == 0) {
                    val *= QSCALE;
                } else if (mat == 1) {
                    val += rel_h[dd * 32 + (n >> 5)] + rel_w[dd * 32 + (n & 31)];
                }
                vals[c] = val;
            }
            *(float4*)&out[obase + (size_t)o * NDIM + nb] =
                make_float4(vals[0], vals[1], vals[2], vals[3]);
        }
    }
}

// ---------------------------------------------------------------------------
// Kernel 2: flash attention. Ti=256 queries, Tj=64 keys, 256 threads (32x8).
// Per-thread 8x8 S fragment + 8x8 O fragment (1.0 B smem / FMA).
// 16 warps/SM (1 CTA, 164 KB smem) -> 2x occupancy vs R4's 8 warps/SM.
// smem layout (floats): Qs[64][260] | Ks[64][68] | PT[64][260] | Vs[64][68]
// ---------------------------------------------------------------------------
#define QS_STRIDE 260
#define KS_STRIDE 68
#define QS_OFF    0
#define KS_OFF    16640
#define PT_OFF    20992
#define VS_OFF    37632
#define SMEM_FLOATS 41984   // 167,936 bytes

__global__ __launch_bounds__(256, 1) void attn_kernel(float* __restrict__ out)
{
    extern __shared__ float sm[];
    float* Qs = sm + QS_OFF;   // [d=64][i=256]
    float* Ks = sm + KS_OFF;   // [d=64][j=64]
    float* PT = sm + PT_OFF;   // [j=64][i=256]
    float* Vs = sm + VS_OFF;   // [j=64][dd=64]

    const int bh = blockIdx.y;
    const int i0 = blockIdx.x * 256;

    const float* __restrict__ qp = g_q + (size_t)bh * DHEAD * NDIM;
    const float* __restrict__ kp = g_k + (size_t)bh * DHEAD * NDIM;
    const float* __restrict__ vp = g_v + (size_t)bh * DHEAD * NDIM;

    const int tid = threadIdx.x;
    const int tc  = tid & 7;        // 0..7  (j / dd groups)
    const int tr  = tid >> 3;       // 0..31 (i groups)

    // Load Q tile [d][i0..i0+255]  (64x256 floats = 4096 float4)
    for (int t = tid; t < 4096; t += 256) {
        const int d  = t >> 6;
        const int i4 = (t & 63) << 2;
        *(float4*)&Qs[d * QS_STRIDE + i4] = *(const float4*)&qp[(size_t)d * NDIM + i0 + i4];
    }

    float m[8], l[8], o[8][8];
#pragma unroll
    for (int r = 0; r < 8; r++) {
        m[r] = -INFINITY;
        l[r] = 0.f;
#pragma unroll
        for (int c = 0; c < 8; c++) o[r][c] = 0.f;
    }

    for (int jt = 0; jt < NDIM / 64; jt++) {
        const int j0 = jt * 64;

        // Load K tile [d][j] (64x64 = 1024 float4)
        for (int t = tid; t < 1024; t += 256) {
            const int d  = t >> 4;
            const int j4 = (t & 15) << 2;
            *(float4*)&Ks[d * KS_STRIDE + j4] = *(const float4*)&kp[(size_t)d * NDIM + j0 + j4];
        }
        // Load V tile transposed [j][dd] (64x64 scalars)
        for (int t = tid; t < 4096; t += 256) {
            const int dd = t >> 6;
            const int j  = t & 63;
            Vs[j * KS_STRIDE + dd] = vp[(size_t)dd * NDIM + j0 + j];
        }
        __syncthreads();   // K, V (and Q on first iter; prev PV done) ready

        // S = Q^T K  (8x8 per thread)
        float s[8][8];
#pragma unroll
        for (int r = 0; r < 8; r++)
#pragma unroll
            for (int c = 0; c < 8; c++) s[r][c] = 0.f;

#pragma unroll 8
        for (int d = 0; d < 64; d++) {
            float4 qa = *(const float4*)&Qs[d * QS_STRIDE + 4 * tr];
            float4 qb = *(const float4*)&Qs[d * QS_STRIDE + 128 + 4 * tr];
            float4 ka = *(const float4*)&Ks[d * KS_STRIDE + 4 * tc];
            float4 kb = *(const float4*)&Ks[d * KS_STRIDE + 32 + 4 * tc];
            float a[8] = {qa.x, qa.y, qa.z, qa.w, qb.x, qb.y, qb.z, qb.w};
            float kv[8] = {ka.x, ka.y, ka.z, ka.w, kb.x, kb.y, kb.z, kb.w};
#pragma unroll
            for (int r = 0; r < 8; r++)
#pragma unroll
                for (int c = 0; c < 8; c++)
                    s[r][c] += a[r] * kv[c];
        }

        // Online softmax: reduce over the 8-lane column group (lanes differ in tc)
#pragma unroll
        for (int r = 0; r < 8; r++) {
            float mt = s[r][0];
#pragma unroll
            for (int c = 1; c < 8; c++) mt = fmaxf(mt, s[r][c]);
            mt = fmaxf(mt, __shfl_xor_sync(0xffffffffu, mt, 1));
            mt = fmaxf(mt, __shfl_xor_sync(0xffffffffu, mt, 2));
            mt = fmaxf(mt, __shfl_xor_sync(0xffffffffu, mt, 4));
            const float mn = fmaxf(m[r], mt);
            const float alpha = __expf(m[r] - mn);
            m[r] = mn;
            float rs = 0.f;
#pragma unroll
            for (int c = 0; c < 8; c++) {
                s[r][c] = __expf(s[r][c] - mn);
                rs += s[r][c];
            }
            rs += __shfl_xor_sync(0xffffffffu, rs, 1);
            rs += __shfl_xor_sync(0xffffffffu, rs, 2);
            rs += __shfl_xor_sync(0xffffffffu, rs, 4);
            l[r] = l[r] * alpha + rs;
#pragma unroll
            for (int c = 0; c < 8; c++) o[r][c] *= alpha;
        }

        // Write P transposed: PT[j][i] (float4 over i)
#pragma unroll
        for (int rj = 0; rj < 8; rj++) {
            const int jv = (rj < 4) ? (4 * tc + rj) : (32 + 4 * tc + (rj - 4));
            *(float4*)&PT[jv * QS_STRIDE + 4 * tr] =
                make_float4(s[0][rj], s[1][rj], s[2][rj], s[3][rj]);
            *(float4*)&PT[jv * QS_STRIDE + 128 + 4 * tr] =
                make_float4(s[4][rj], s[5][rj], s[6][rj], s[7][rj]);
        }
        __syncthreads();   // PT complete

        // O += P V   (8x8 per thread, all LDS.128)
#pragma unroll 8
        for (int j = 0; j < 64; j++) {
            float4 pa = *(const float4*)&PT[j * QS_STRIDE + 4 * tr];
            float4 pb = *(const float4*)&PT[j * QS_STRIDE + 128 + 4 * tr];
            float4 va = *(const float4*)&Vs[j * KS_STRIDE + 4 * tc];
            float4 vb = *(const float4*)&Vs[j * KS_STRIDE + 32 + 4 * tc];
            float p[8] = {pa.x, pa.y, pa.z, pa.w, pb.x, pb.y, pb.z, pb.w};
            float vv[8] = {va.x, va.y, va.z, va.w, vb.x, vb.y, vb.z, vb.w};
#pragma unroll
            for (int r = 0; r < 8; r++)
#pragma unroll
                for (int c = 0; c < 8; c++)
                    o[r][c] += p[r] * vv[c];
        }
        __syncthreads();   // PV done; Ks/Vs/PT reusable next iter
    }

    // Epilogue: out[bh][i][dd] = o / l
    float* __restrict__ outp = out + (size_t)bh * NDIM * DHEAD;
#pragma unroll
    for (int r = 0; r < 8; r++) {
        const float inv = 1.0f / l[r];
        const int i = i0 + ((r < 4) ? (4 * tr + r) : (128 + 4 * tr + (r - 4)));
        *(float4*)&outp[(size_t)i * DHEAD + 4 * tc] =
            make_float4(o[r][0] * inv, o[r][1] * inv, o[r][2] * inv, o[r][3] * inv);
        *(float4*)&outp[(size_t)i * DHEAD + 32 + 4 * tc] =
            make_float4(o[r][4] * inv, o[r][5] * inv, o[r][6] * inv, o[r][7] * inv);
    }
}

// ---------------------------------------------------------------------------
extern "C" void kernel_launch(void* const* d_in, const int* in_sizes, int n_in,
                              void* d_out, int out_size)
{
    const float* x     = (const float*)d_in[0];
    const float* Wq    = (const float*)d_in[1];
    const float* bq    = (const float*)d_in[2];
    const float* Wk    = (const float*)d_in[3];
    const float* bk    = (const float*)d_in[4];
    const float* Wv    = (const float*)d_in[5];
    const float* bv    = (const float*)d_in[6];
    const float* rel_h = (const float*)d_in[7];
    const float* rel_w = (const float*)d_in[8];
    float* out = (float*)d_out;

    cudaFuncSetAttribute(attn_kernel,
                         cudaFuncAttributeMaxDynamicSharedMemorySize,
                         SMEM_FLOATS * 4);

    dim3 g1(NDIM / 128, CDIM / 128, 3 * BDIM);
    qkv_gemm_kernel<<<g1, 256>>>(x, Wq, bq, Wk, bk, Wv, bv, rel_h, rel_w);

    dim3 g2(NDIM / 256, BDIM * NHEADS);
    attn_kernel<<<g2, 256, SMEM_FLOATS * 4>>>(out);
}

// round 10
// speedup vs baseline: 1.5736x; 1.5736x over previous
#include <cstdint>
#include <stdint.h>
#include <cuda_runtime.h>
#include <cuda_bf16.h>
#include <math.h>

// Problem constants
#define BDIM 16
#define CDIM 512
#define NDIM 1024
#define NHEADS 8
#define DHEAD 64
#define QSCALE 0.125f
#define NBH (BDIM * NHEADS)

// fp32 scratch from the QKV GEMM: layout [bh][d][n]  (== [B][C][N])
__device__ float g_q[BDIM * CDIM * NDIM];
__device__ float g_k[BDIM * CDIM * NDIM];
__device__ float g_v[BDIM * CDIM * NDIM];

// split-bf16 operand arrays for the mma attention
__device__ __nv_bfloat16 g_qh[NBH * NDIM * DHEAD];  // [bh][i][d]
__device__ __nv_bfloat16 g_ql[NBH * NDIM * DHEAD];
__device__ __nv_bfloat16 g_kh[NBH * NDIM * DHEAD];  // [bh][j][d]
__device__ __nv_bfloat16 g_kl[NBH * NDIM * DHEAD];
__device__ __nv_bfloat16 g_vh[NBH * DHEAD * NDIM];  // [bh][d][j]
__device__ __nv_bfloat16 g_vl[NBH * DHEAD * NDIM];

// ---------------------------------------------------------------------------
// split a pair of floats into packed (hi,hi) and (lo,lo) bf16x2 words
// ---------------------------------------------------------------------------
__device__ __forceinline__ void splitbf(float a, float b,
                                        uint32_t& hi, uint32_t& lo)
{
    __nv_bfloat16 ah = __float2bfloat16_rn(a);
    __nv_bfloat16 bh = __float2bfloat16_rn(b);
    __nv_bfloat16 al = __float2bfloat16_rn(a - __bfloat162float(ah));
    __nv_bfloat16 bl = __float2bfloat16_rn(b - __bfloat162float(bh));
    __nv_bfloat162 h; h.x = ah; h.y = bh;
    __nv_bfloat162 l; l.x = al; l.y = bl;
    hi = *(uint32_t*)&h;
    lo = *(uint32_t*)&l;
}

#define MMA_BF16(C, A, b0, b1)                                               \
    asm volatile(                                                            \
        "mma.sync.aligned.m16n8k16.row.col.f32.bf16.bf16.f32 "               \
        "{%0,%1,%2,%3},{%4,%5,%6,%7},{%8,%9},{%0,%1,%2,%3};\n"               \
        : "+f"((C)[0]), "+f"((C)[1]), "+f"((C)[2]), "+f"((C)[3])             \
        : "r"((A)[0]), "r"((A)[1]), "r"((A)[2]), "r"((A)[3]),                \
          "r"(b0), "r"(b1))

// ---------------------------------------------------------------------------
// Kernel 1: fused QKV projection (UNCHANGED, proven) — fp32 out to g_q/g_k/g_v
// ---------------------------------------------------------------------------
__global__ __launch_bounds__(256) void qkv_gemm_kernel(
    const float* __restrict__ x,
    const float* __restrict__ Wq, const float* __restrict__ bq,
    const float* __restrict__ Wk, const float* __restrict__ bk,
    const float* __restrict__ Wv, const float* __restrict__ bv,
    const float* __restrict__ rel_h, const float* __restrict__ rel_w)
{
    const int mat = blockIdx.z >> 4;
    const int b   = blockIdx.z & 15;

    const float* __restrict__ W    = (mat == 0) ? Wq : (mat == 1) ? Wk : Wv;
    const float* __restrict__ bias = (mat == 0) ? bq : (mat == 1) ? bk : bv;
    float* __restrict__ out        = (mat == 0) ? g_q : (mat == 1) ? g_k : g_v;

    const int o0 = blockIdx.y * 128;
    const int n0 = blockIdx.x * 128;

    __shared__ float Ws[16 * 132];
    __shared__ float Xs[16 * 132];

    const int tid = threadIdx.x;
    const int tr  = tid >> 4;
    const int tc  = tid & 15;

    float acc[8][8];
#pragma unroll
    for (int r = 0; r < 8; r++)
#pragma unroll
        for (int c = 0; c < 8; c++) acc[r][c] = 0.f;

    const float* __restrict__ xb = x + (size_t)b * CDIM * NDIM;

    const int wrow = tid >> 1;
    const int wk   = (tid & 1) * 8;
    const int xrow = tid >> 4;
    const int xcol = (tid & 15) * 8;

    float4 w0 = *(const float4*)&W[(size_t)(o0 + wrow) * CDIM + wk];
    float4 w1 = *(const float4*)&W[(size_t)(o0 + wrow) * CDIM + wk + 4];
    float4 x0 = *(const float4*)&xb[(size_t)xrow * NDIM + n0 + xcol];
    float4 x1 = *(const float4*)&xb[(size_t)xrow * NDIM + n0 + xcol + 4];

    for (int k0 = 0; k0 < CDIM; k0 += 16) {
        __syncthreads();
        Ws[(wk + 0) * 132 + wrow] = w0.x;
        Ws[(wk + 1) * 132 + wrow] = w0.y;
        Ws[(wk + 2) * 132 + wrow] = w0.z;
        Ws[(wk + 3) * 132 + wrow] = w0.w;
        Ws[(wk + 4) * 132 + wrow] = w1.x;
        Ws[(wk + 5) * 132 + wrow] = w1.y;
        Ws[(wk + 6) * 132 + wrow] = w1.z;
        Ws[(wk + 7) * 132 + wrow] = w1.w;
        *(float4*)&Xs[xrow * 132 + xcol]     = x0;
        *(float4*)&Xs[xrow * 132 + xcol + 4] = x1;
        __syncthreads();

        if (k0 + 16 < CDIM) {
            w0 = *(const float4*)&W[(size_t)(o0 + wrow) * CDIM + k0 + 16 + wk];
            w1 = *(const float4*)&W[(size_t)(o0 + wrow) * CDIM + k0 + 16 + wk + 4];
            x0 = *(const float4*)&xb[(size_t)(k0 + 16 + xrow) * NDIM + n0 + xcol];
            x1 = *(const float4*)&xb[(size_t)(k0 + 16 + xrow) * NDIM + n0 + xcol + 4];
        }

#pragma unroll 8
        for (int kk = 0; kk < 16; kk++) {
            float4 a0 = *(const float4*)&Ws[kk * 132 + 4 * tr];
            float4 a1 = *(const float4*)&Ws[kk * 132 + 64 + 4 * tr];
            float4 b0 = *(const float4*)&Xs[kk * 132 + 4 * tc];
            float4 b1 = *(const float4*)&Xs[kk * 132 + 64 + 4 * tc];
            float a[8] = {a0.x, a0.y, a0.z, a0.w, a1.x, a1.y, a1.z, a1.w};
            float bb[8] = {b0.x, b0.y, b0.z, b0.w, b1.x, b1.y, b1.z, b1.w};
#pragma unroll
            for (int r = 0; r < 8; r++)
#pragma unroll
                for (int c = 0; c < 8; c++)
                    acc[r][c] += a[r] * bb[c];
        }
    }

    const size_t obase = (size_t)b * CDIM * NDIM;
#pragma unroll
    for (int r = 0; r < 8; r++) {
        const int o  = o0 + ((r < 4) ? (4 * tr + r) : (64 + 4 * tr + (r - 4)));
        const float bi = bias[o];
        const int dd = o & 63;
#pragma unroll
        for (int g = 0; g < 2; g++) {
            const int nb = n0 + (g ? (64 + 4 * tc) : (4 * tc));
            float vals[4];
#pragma unroll
            for (int c = 0; c < 4; c++) {
                const int n = nb + c;
                float val = acc[r][g * 4 + c] + bi;
                if (mat == 0) {
                    val *= QSCALE;
                } else if (mat == 1) {
                    val += rel_h[dd * 32 + (n >> 5)] + rel_w[dd * 32 + (n & 31)];
                }
                vals[c] = val;
            }
            *(float4*)&out[obase + (size_t)o * NDIM + nb] =
                make_float4(vals[0], vals[1], vals[2], vals[3]);
        }
    }
}

// ---------------------------------------------------------------------------
// Conversion: q,k fp32 [bh][d][n] -> split-bf16 [bh][row][d] (transposed).
// One thread handles one packed word (d=2w, 2w+1) of one row. Reads coalesced.
// ---------------------------------------------------------------------------
__global__ __launch_bounds__(256) void conv_qk_kernel()
{
    const size_t idx = (size_t)blockIdx.x * 256 + threadIdx.x;
    // bits: i:10 | w:5 | bh:7 | which:1   -> 2*128*32*1024 = 8,388,608 threads
    const int i     = (int)(idx & 1023);
    const int w     = (int)((idx >> 10) & 31);
    const int bh    = (int)((idx >> 15) & 127);
    const int which = (int)(idx >> 22);

    const float* __restrict__ src = which ? g_k : g_q;
    const float a = src[(((size_t)bh * DHEAD + 2 * w) << 10) + i];
    const float b = src[(((size_t)bh * DHEAD + 2 * w + 1) << 10) + i];

    uint32_t hi, lo;
    splitbf(a, b, hi, lo);

    const size_t dst = ((size_t)bh * NDIM + i) * 32 + w;   // word index
    ((uint32_t*)(which ? g_kh : g_qh))[dst] = hi;
    ((uint32_t*)(which ? g_kl : g_ql))[dst] = lo;
}

// ---------------------------------------------------------------------------
// Conversion: v fp32 [bh][d][j] -> split-bf16 same layout (pure convert).
// ---------------------------------------------------------------------------
__global__ __launch_bounds__(256) void conv_v_kernel()
{
    const size_t idx = (size_t)blockIdx.x * 256 + threadIdx.x;  // float4 index
    const float4 v = ((const float4*)g_v)[idx];
    uint32_t h0, l0, h1, l1;
    splitbf(v.x, v.y, h0, l0);
    splitbf(v.z, v.w, h1, l1);
    ((uint2*)g_vh)[idx] = make_uint2(h0, h1);
    ((uint2*)g_vl)[idx] = make_uint2(l0, l1);
}

// ---------------------------------------------------------------------------
// Kernel 2: flash attention with split-bf16 mma.sync.m16n8k16.
// CTA: 128 threads (4 warps). Ti=64 (16 rows/warp), Tj=64, d=64.
// smem rows stride 36 words -> all fragment LDS land on banks 4g+t (conflict-
// free). P stays in registers (S C-frags are PV A-frags). 2 barriers/tile.
// ---------------------------------------------------------------------------
#define ROWW 36                      // words per smem row
#define ARR  (64 * ROWW)             // 2304 words per array
#define ATTN_SMEM_WORDS (6 * ARR)    // 13824 words = 55296 B

__global__ __launch_bounds__(128) void attn_mma_kernel(float* __restrict__ out)
{
    extern __shared__ uint32_t sw[];
    uint32_t* qsh = sw;
    uint32_t* qsl = sw + ARR;
    uint32_t* ksh = sw + 2 * ARR;
    uint32_t* ksl = sw + 3 * ARR;
    uint32_t* vsh = sw + 4 * ARR;
    uint32_t* vsl = sw + 5 * ARR;

    const int bh = blockIdx.y;
    const int i0 = blockIdx.x * 64;

    const int tid  = threadIdx.x;
    const int lane = tid & 31;
    const int warp = tid >> 5;
    const int g    = lane >> 2;   // 0..7
    const int t    = lane & 3;    // 0..3

    // ---- load Q tile (rows i0..i0+63, 32 words each) into smem ----
    {
        const uint4* qh = (const uint4*)(g_qh + ((size_t)bh * NDIM + i0) * DHEAD);
        const uint4* ql = (const uint4*)(g_ql + ((size_t)bh * NDIM + i0) * DHEAD);
        for (int kk = tid; kk < 512; kk += 128) {
            const int r = kk >> 3, c = kk & 7;
            *(uint4*)&qsh[r * ROWW + c * 4] = qh[r * 8 + c];
            *(uint4*)&qsl[r * ROWW + c * 4] = ql[r * 8 + c];
        }
    }
    __syncthreads();

    // ---- hoist Q A-fragments (reused across all 16 j-tiles) ----
    uint32_t Ah[4][4], Al[4][4];
    {
        const int qr = warp * 16 + g;
#pragma unroll
        for (int ks = 0; ks < 4; ks++) {
            Ah[ks][0] = qsh[qr * ROWW + 8 * ks + t];
            Ah[ks][1] = qsh[(qr + 8) * ROWW + 8 * ks + t];
            Ah[ks][2] = qsh[qr * ROWW + 8 * ks + t + 4];
            Ah[ks][3] = qsh[(qr + 8) * ROWW + 8 * ks + t + 4];
            Al[ks][0] = qsl[qr * ROWW + 8 * ks + t];
            Al[ks][1] = qsl[(qr + 8) * ROWW + 8 * ks + t];
            Al[ks][2] = qsl[qr * ROWW + 8 * ks + t + 4];
            Al[ks][3] = qsl[(qr + 8) * ROWW + 8 * ks + t + 4];
        }
    }

    float m0 = -INFINITY, m1 = -INFINITY, l0 = 0.f, l1 = 0.f;
    float O[8][4];
#pragma unroll
    for (int nt = 0; nt < 8; nt++)
#pragma unroll
        for (int c = 0; c < 4; c++) O[nt][c] = 0.f;

    for (int jt = 0; jt < NDIM / 64; jt++) {
        const int j0 = jt * 64;

        // ---- load K tile [j][d] and V tile [dd][j0..j0+63] ----
        {
            const uint4* kh = (const uint4*)(g_kh + ((size_t)bh * NDIM + j0) * DHEAD);
            const uint4* kl = (const uint4*)(g_kl + ((size_t)bh * NDIM + j0) * DHEAD);
            const uint4* vh = (const uint4*)(g_vh + (size_t)bh * DHEAD * NDIM + j0);
            const uint4* vl = (const uint4*)(g_vl + (size_t)bh * DHEAD * NDIM + j0);
            for (int kk = tid; kk < 512; kk += 128) {
                const int r = kk >> 3, c = kk & 7;
                *(uint4*)&ksh[r * ROWW + c * 4] = kh[r * 8 + c];
                *(uint4*)&ksl[r * ROWW + c * 4] = kl[r * 8 + c];
                *(uint4*)&vsh[r * ROWW + c * 4] = vh[r * 128 + c];  // row stride 1024 bf16 = 128 uint4
                *(uint4*)&vsl[r * ROWW + c * 4] = vl[r * 128 + c];
            }
        }
        __syncthreads();

        // ---- S = q'^T k' : 8 n-tiles x 4 k-steps x 3 split-mma ----
        float S[8][4];
#pragma unroll
        for (int nt = 0; nt < 8; nt++)
#pragma unroll
            for (int c = 0; c < 4; c++) S[nt][c] = 0.f;

#pragma unroll
        for (int nt = 0; nt < 8; nt++) {
            const int kr = (8 * nt + g) * ROWW;
#pragma unroll
            for (int ks = 0; ks < 4; ks++) {
                const uint32_t b0h = ksh[kr + 8 * ks + t];
                const uint32_t b1h = ksh[kr + 8 * ks + t + 4];
                const uint32_t b0l = ksl[kr + 8 * ks + t];
                const uint32_t b1l = ksl[kr + 8 * ks + t + 4];
                MMA_BF16(S[nt], Ah[ks], b0h, b1h);
                MMA_BF16(S[nt], Ah[ks], b0l, b1l);
                MMA_BF16(S[nt], Al[ks], b0h, b1h);
            }
        }

        // ---- online softmax (rows g and g+8; col quad = lanes t) ----
        float mx0 = S[0][0], mx1 = S[0][2];
#pragma unroll
        for (int nt = 0; nt < 8; nt++) {
            mx0 = fmaxf(mx0, fmaxf(S[nt][0], S[nt][1]));
            mx1 = fmaxf(mx1, fmaxf(S[nt][2], S[nt][3]));
        }
        mx0 = fmaxf(mx0, __shfl_xor_sync(0xffffffffu, mx0, 1));
        mx0 = fmaxf(mx0, __shfl_xor_sync(0xffffffffu, mx0, 2));
        mx1 = fmaxf(mx1, __shfl_xor_sync(0xffffffffu, mx1, 1));
        mx1 = fmaxf(mx1, __shfl_xor_sync(0xffffffffu, mx1, 2));

        const float mn0 = fmaxf(m0, mx0);
        const float mn1 = fmaxf(m1, mx1);
        const float al0 = __expf(m0 - mn0);
        const float al1 = __expf(m1 - mn1);
        m0 = mn0; m1 = mn1;

        float rs0 = 0.f, rs1 = 0.f;
#pragma unroll
        for (int nt = 0; nt < 8; nt++) {
            S[nt][0] = __expf(S[nt][0] - mn0); rs0 += S[nt][0];
            S[nt][1] = __expf(S[nt][1] - mn0); rs0 += S[nt][1];
            S[nt][2] = __expf(S[nt][2] - mn1); rs1 += S[nt][2];
            S[nt][3] = __expf(S[nt][3] - mn1); rs1 += S[nt][3];
        }
        rs0 += __shfl_xor_sync(0xffffffffu, rs0, 1);
        rs0 += __shfl_xor_sync(0xffffffffu, rs0, 2);
        rs1 += __shfl_xor_sync(0xffffffffu, rs1, 1);
        rs1 += __shfl_xor_sync(0xffffffffu, rs1, 2);
        l0 = l0 * al0 + rs0;
        l1 = l1 * al1 + rs1;

#pragma unroll
        for (int nt = 0; nt < 8; nt++) {
            O[nt][0] *= al0; O[nt][1] *= al0;
            O[nt][2] *= al1; O[nt][3] *= al1;
        }

        // ---- O += P V : S C-frags become PV A-frags in registers ----
#pragma unroll
        for (int kk = 0; kk < 4; kk++) {
            uint32_t Ph[4], Pl[4];
            splitbf(S[2 * kk][0],     S[2 * kk][1],     Ph[0], Pl[0]);
            splitbf(S[2 * kk][2],     S[2 * kk][3],     Ph[1], Pl[1]);
            splitbf(S[2 * kk + 1][0], S[2 * kk + 1][1], Ph[2], Pl[2]);
            splitbf(S[2 * kk + 1][2], S[2 * kk + 1][3], Ph[3], Pl[3]);
#pragma unroll
            for (int nt = 0; nt < 8; nt++) {
                const int vr = (8 * nt + g) * ROWW;
                const uint32_t b0h = vsh[vr + 8 * kk + t];
                const uint32_t b1h = vsh[vr + 8 * kk + t + 4];
                const uint32_t b0l = vsl[vr + 8 * kk + t];
                const uint32_t b1l = vsl[vr + 8 * kk + t + 4];
                MMA_BF16(O[nt], Ph, b0h, b1h);
                MMA_BF16(O[nt], Ph, b0l, b1l);
                MMA_BF16(O[nt], Pl, b0h, b1h);
            }
        }
        __syncthreads();   // PV done before next tile overwrites K/V
    }

    // ---- epilogue: out[bh][i][dd] = O / l ----
    const float inv0 = 1.0f / l0;
    const float inv1 = 1.0f / l1;
    const int i = i0 + warp * 16 + g;
    float* __restrict__ op0 = out + ((size_t)bh * NDIM + i) * DHEAD;
    float* __restrict__ op1 = out + ((size_t)bh * NDIM + i + 8) * DHEAD;
#pragma unroll
    for (int nt = 0; nt < 8; nt++) {
        const int dd = 8 * nt + 2 * t;
        *(float2*)&op0[dd] = make_float2(O[nt][0] * inv0, O[nt][1] * inv0);
        *(float2*)&op1[dd] = make_float2(O[nt][2] * inv1, O[nt][3] * inv1);
    }
}

// ---------------------------------------------------------------------------
extern "C" void kernel_launch(void* const* d_in, const int* in_sizes, int n_in,
                              void* d_out, int out_size)
{
    const float* x     = (const float*)d_in[0];
    const float* Wq    = (const float*)d_in[1];
    const float* bq    = (const float*)d_in[2];
    const float* Wk    = (const float*)d_in[3];
    const float* bk    = (const float*)d_in[4];
    const float* Wv    = (const float*)d_in[5];
    const float* bv    = (const float*)d_in[6];
    const float* rel_h = (const float*)d_in[7];
    const float* rel_w = (const float*)d_in[8];
    float* out = (float*)d_out;

    cudaFuncSetAttribute(attn_mma_kernel,
                         cudaFuncAttributeMaxDynamicSharedMemorySize,
                         ATTN_SMEM_WORDS * 4);

    // 1) QKV projections (fp32, unchanged)
    dim3 g1(NDIM / 128, CDIM / 128, 3 * BDIM);
    qkv_gemm_kernel<<<g1, 256>>>(x, Wq, bq, Wk, bk, Wv, bv, rel_h, rel_w);

    // 2) split-bf16 conversions
    conv_qk_kernel<<<(2 * NBH * 32 * NDIM) / 256, 256>>>();
    conv_v_kernel<<<(NBH * DHEAD * NDIM / 4) / 256, 256>>>();

    // 3) tensor-core flash attention
    dim3 g2(NDIM / 64, NBH);
    attn_mma_kernel<<<g2, 128, ATTN_SMEM_WORDS * 4>>>(out);
}

// round 12
// speedup vs baseline: 2.0892x; 1.3277x over previous
#include <cstdint>
#include <stdint.h>
#include <cuda_runtime.h>
#include <cuda_bf16.h>
#include <math.h>

// Problem constants
#define BDIM 16
#define CDIM 512
#define NDIM 1024
#define NHEADS 8
#define DHEAD 64
#define QSCALE 0.125f
#define NBH (BDIM * NHEADS)

// fp32 scratch from the QKV GEMM: layout [bh][d][n]  (== [B][C][N])
__device__ float g_q[BDIM * CDIM * NDIM];
__device__ float g_k[BDIM * CDIM * NDIM];
__device__ float g_v[BDIM * CDIM * NDIM];

// split-bf16 operand arrays for the mma attention
__device__ __nv_bfloat16 g_qh[NBH * NDIM * DHEAD];  // [bh][i][d]
__device__ __nv_bfloat16 g_ql[NBH * NDIM * DHEAD];
__device__ __nv_bfloat16 g_kh[NBH * NDIM * DHEAD];  // [bh][j][d]
__device__ __nv_bfloat16 g_kl[NBH * NDIM * DHEAD];
__device__ __nv_bfloat16 g_vh[NBH * DHEAD * NDIM];  // [bh][d][j]
__device__ __nv_bfloat16 g_vl[NBH * DHEAD * NDIM];

// ---------------------------------------------------------------------------
__device__ __forceinline__ void splitbf(float a, float b,
                                        uint32_t& hi, uint32_t& lo)
{
    __nv_bfloat16 ah = __float2bfloat16_rn(a);
    __nv_bfloat16 bh = __float2bfloat16_rn(b);
    __nv_bfloat16 al = __float2bfloat16_rn(a - __bfloat162float(ah));
    __nv_bfloat16 bl = __float2bfloat16_rn(b - __bfloat162float(bh));
    __nv_bfloat162 h; h.x = ah; h.y = bh;
    __nv_bfloat162 l; l.x = al; l.y = bl;
    hi = *(uint32_t*)&h;
    lo = *(uint32_t*)&l;
}

#define MMA_BF16(C, A, b0, b1)                                               \
    asm volatile(                                                            \
        "mma.sync.aligned.m16n8k16.row.col.f32.bf16.bf16.f32 "               \
        "{%0,%1,%2,%3},{%4,%5,%6,%7},{%8,%9},{%0,%1,%2,%3};\n"               \
        : "+f"((C)[0]), "+f"((C)[1]), "+f"((C)[2]), "+f"((C)[3])             \
        : "r"((A)[0]), "r"((A)[1]), "r"((A)[2]), "r"((A)[3]),                \
          "r"(b0), "r"(b1))

// ---------------------------------------------------------------------------
// Kernel 1: QKV projection via split-bf16 tensor cores.
// C[o(128)][n(128)] per CTA, k=512 in KC=32 chunks, register prefetch.
// FIX vs R10: W load now covers the FULL 32-c chunk per row
//   (2 threads/row x 16 floats; was 2 x 8 = half the chunk -> garbage).
// ---------------------------------------------------------------------------
#define KC 32
#define GROWW 20

__global__ __launch_bounds__(256) void qkv_gemm_mma_kernel(
    const float* __restrict__ x,
    const float* __restrict__ Wq, const float* __restrict__ bq,
    const float* __restrict__ Wk, const float* __restrict__ bk,
    const float* __restrict__ Wv, const float* __restrict__ bv,
    const float* __restrict__ rel_h, const float* __restrict__ rel_w)
{
    const int mat = blockIdx.z >> 4;   // 0=q, 1=k, 2=v
    const int b   = blockIdx.z & 15;

    const float* __restrict__ W    = (mat == 0) ? Wq : (mat == 1) ? Wk : Wv;
    const float* __restrict__ bias = (mat == 0) ? bq : (mat == 1) ? bk : bv;
    float* __restrict__ out        = (mat == 0) ? g_q : (mat == 1) ? g_k : g_v;

    const int o0 = blockIdx.y * 128;
    const int n0 = blockIdx.x * 128;

    __shared__ uint32_t Wh[128 * GROWW], Wl[128 * GROWW];
    __shared__ uint32_t Xh[128 * GROWW], Xl[128 * GROWW];

    const int tid  = threadIdx.x;
    const int lane = tid & 31;
    const int warp = tid >> 5;
    const int g    = lane >> 2;
    const int t    = lane & 3;
    const int wm   = (warp >> 2) * 64;   // warp o offset in tile
    const int wn   = (warp & 3) * 32;    // warp n offset in tile

    float acc[4][4][4];
#pragma unroll
    for (int mt = 0; mt < 4; mt++)
#pragma unroll
        for (int nt = 0; nt < 4; nt++)
#pragma unroll
            for (int c = 0; c < 4; c++) acc[mt][nt][c] = 0.f;

    const float* __restrict__ xb = x + (size_t)b * CDIM * NDIM;

    // load assignments
    const int lo_w = tid >> 1;             // 0..127 (o row of W)
    const int lc_w = (tid & 1) * 16;       // c offset 0/16 (16 floats each)
    const int lc_x = 2 * (tid & 15);       // c row pair for X (0..30)
    const int ln_x = ((tid >> 4) & 15) * 4;// n offset (0..60; +64 second half)

    // prefetch chunk 0
    float4 pw0 = *(const float4*)&W[(size_t)(o0 + lo_w) * CDIM + lc_w];
    float4 pw1 = *(const float4*)&W[(size_t)(o0 + lo_w) * CDIM + lc_w + 4];
    float4 pw2 = *(const float4*)&W[(size_t)(o0 + lo_w) * CDIM + lc_w + 8];
    float4 pw3 = *(const float4*)&W[(size_t)(o0 + lo_w) * CDIM + lc_w + 12];
    float4 px00 = *(const float4*)&xb[(size_t)lc_x * NDIM + n0 + ln_x];
    float4 px01 = *(const float4*)&xb[(size_t)(lc_x + 1) * NDIM + n0 + ln_x];
    float4 px10 = *(const float4*)&xb[(size_t)lc_x * NDIM + n0 + ln_x + 64];
    float4 px11 = *(const float4*)&xb[(size_t)(lc_x + 1) * NDIM + n0 + ln_x + 64];

    for (int k0 = 0; k0 < CDIM; k0 += KC) {
        __syncthreads();
        // ---- store W (split, k-contiguous words): 8 words = full 16 c's ----
        {
            uint32_t h0, h1, h2, h3, h4, h5, h6, h7;
            uint32_t l0, l1, l2, l3, l4, l5, l6, l7;
            splitbf(pw0.x, pw0.y, h0, l0); splitbf(pw0.z, pw0.w, h1, l1);
            splitbf(pw1.x, pw1.y, h2, l2); splitbf(pw1.z, pw1.w, h3, l3);
            splitbf(pw2.x, pw2.y, h4, l4); splitbf(pw2.z, pw2.w, h5, l5);
            splitbf(pw3.x, pw3.y, h6, l6); splitbf(pw3.z, pw3.w, h7, l7);
            const int wb = lo_w * GROWW + lc_w / 2;   // word base (0 or 8)
            *(uint4*)&Wh[wb]     = make_uint4(h0, h1, h2, h3);
            *(uint4*)&Wh[wb + 4] = make_uint4(h4, h5, h6, h7);
            *(uint4*)&Wl[wb]     = make_uint4(l0, l1, l2, l3);
            *(uint4*)&Wl[wb + 4] = make_uint4(l4, l5, l6, l7);
        }
        // ---- store X transposed (c-pair packed per word) ----
        {
            const int cp = tid & 15;
            uint32_t hi, lo;
            splitbf(px00.x, px01.x, hi, lo);
            Xh[(ln_x + 0) * GROWW + cp] = hi; Xl[(ln_x + 0) * GROWW + cp] = lo;
            splitbf(px00.y, px01.y, hi, lo);
            Xh[(ln_x + 1) * GROWW + cp] = hi; Xl[(ln_x + 1) * GROWW + cp] = lo;
            splitbf(px00.z, px01.z, hi, lo);
            Xh[(ln_x + 2) * GROWW + cp] = hi; Xl[(ln_x + 2) * GROWW + cp] = lo;
            splitbf(px00.w, px01.w, hi, lo);
            Xh[(ln_x + 3) * GROWW + cp] = hi; Xl[(ln_x + 3) * GROWW + cp] = lo;
            splitbf(px10.x, px11.x, hi, lo);
            Xh[(ln_x + 64) * GROWW + cp] = hi; Xl[(ln_x + 64) * GROWW + cp] = lo;
            splitbf(px10.y, px11.y, hi, lo);
            Xh[(ln_x + 65) * GROWW + cp] = hi; Xl[(ln_x + 65) * GROWW + cp] = lo;
            splitbf(px10.z, px11.z, hi, lo);
            Xh[(ln_x + 66) * GROWW + cp] = hi; Xl[(ln_x + 66) * GROWW + cp] = lo;
            splitbf(px10.w, px11.w, hi, lo);
            Xh[(ln_x + 67) * GROWW + cp] = hi; Xl[(ln_x + 67) * GROWW + cp] = lo;
        }
        __syncthreads();

        // ---- prefetch next chunk ----
        if (k0 + KC < CDIM) {
            const int kn = k0 + KC;
            pw0 = *(const float4*)&W[(size_t)(o0 + lo_w) * CDIM + kn + lc_w];
            pw1 = *(const float4*)&W[(size_t)(o0 + lo_w) * CDIM + kn + lc_w + 4];
            pw2 = *(const float4*)&W[(size_t)(o0 + lo_w) * CDIM + kn + lc_w + 8];
            pw3 = *(const float4*)&W[(size_t)(o0 + lo_w) * CDIM + kn + lc_w + 12];
            px00 = *(const float4*)&xb[(size_t)(kn + lc_x) * NDIM + n0 + ln_x];
            px01 = *(const float4*)&xb[(size_t)(kn + lc_x + 1) * NDIM + n0 + ln_x];
            px10 = *(const float4*)&xb[(size_t)(kn + lc_x) * NDIM + n0 + ln_x + 64];
            px11 = *(const float4*)&xb[(size_t)(kn + lc_x + 1) * NDIM + n0 + ln_x + 64];
        }

        // ---- compute: 2 k-steps of 16 ----
#pragma unroll
        for (int ks = 0; ks < 2; ks++) {
            uint32_t Ah[4][4], Al[4][4];
#pragma unroll
            for (int mt = 0; mt < 4; mt++) {
                const int r0 = (wm + mt * 16 + g) * GROWW + ks * 8 + t;
                const int r1 = (wm + mt * 16 + 8 + g) * GROWW + ks * 8 + t;
                Ah[mt][0] = Wh[r0]; Ah[mt][1] = Wh[r1];
                Ah[mt][2] = Wh[r0 + 4]; Ah[mt][3] = Wh[r1 + 4];
                Al[mt][0] = Wl[r0]; Al[mt][1] = Wl[r1];
                Al[mt][2] = Wl[r0 + 4]; Al[mt][3] = Wl[r1 + 4];
            }
            uint32_t Bh[4][2], Bl[4][2];
#pragma unroll
            for (int nt = 0; nt < 4; nt++) {
                const int rr = (wn + nt * 8 + g) * GROWW + ks * 8 + t;
                Bh[nt][0] = Xh[rr]; Bh[nt][1] = Xh[rr + 4];
                Bl[nt][0] = Xl[rr]; Bl[nt][1] = Xl[rr + 4];
            }
#pragma unroll
            for (int mt = 0; mt < 4; mt++)
#pragma unroll
                for (int nt = 0; nt < 4; nt++) {
                    MMA_BF16(acc[mt][nt], Ah[mt], Bh[nt][0], Bh[nt][1]);
                    MMA_BF16(acc[mt][nt], Ah[mt], Bl[nt][0], Bl[nt][1]);
                    MMA_BF16(acc[mt][nt], Al[mt], Bh[nt][0], Bh[nt][1]);
                }
        }
    }

    // ---- epilogue (same math as proven fp32 kernel) ----
    const size_t obase = (size_t)b * CDIM * NDIM;
#pragma unroll
    for (int mt = 0; mt < 4; mt++) {
        const int o_a = o0 + wm + mt * 16 + g;
        const int o_b = o_a + 8;
        const float bia = bias[o_a];
        const float bib = bias[o_b];
        const int dda = o_a & 63;
        const int ddb = o_b & 63;
#pragma unroll
        for (int nt = 0; nt < 4; nt++) {
            const int n = n0 + wn + nt * 8 + 2 * t;
            float v0 = acc[mt][nt][0] + bia;
            float v1 = acc[mt][nt][1] + bia;
            float v2 = acc[mt][nt][2] + bib;
            float v3 = acc[mt][nt][3] + bib;
            if (mat == 0) {
                v0 *= QSCALE; v1 *= QSCALE; v2 *= QSCALE; v3 *= QSCALE;
            } else if (mat == 1) {
                v0 += rel_h[dda * 32 + (n >> 5)] + rel_w[dda * 32 + (n & 31)];
                v1 += rel_h[dda * 32 + ((n + 1) >> 5)] + rel_w[dda * 32 + ((n + 1) & 31)];
                v2 += rel_h[ddb * 32 + (n >> 5)] + rel_w[ddb * 32 + (n & 31)];
                v3 += rel_h[ddb * 32 + ((n + 1) >> 5)] + rel_w[ddb * 32 + ((n + 1) & 31)];
            }
            *(float2*)&out[obase + (size_t)o_a * NDIM + n] = make_float2(v0, v1);
            *(float2*)&out[obase + (size_t)o_b * NDIM + n] = make_float2(v2, v3);
        }
    }
}

// ---------------------------------------------------------------------------
// Conversion: q,k fp32 [bh][d][n] -> split-bf16 [bh][i][d] via smem-tile
// transpose (coalesced both phases).
// ---------------------------------------------------------------------------
__global__ __launch_bounds__(256) void conv_qk_t_kernel()
{
    const int n0    = blockIdx.x * 64;
    const int bh    = blockIdx.y;
    const int which = blockIdx.z;

    const float* __restrict__ src =
        (which ? g_k : g_q) + (size_t)bh * DHEAD * NDIM;

    __shared__ float Ts[64 * 65];   // [n][d]
    const int tid = threadIdx.x;

    for (int tt = tid; tt < 1024; tt += 256) {
        const int d  = tt >> 4;
        const int c4 = (tt & 15) * 4;
        const float4 v = *(const float4*)&src[(size_t)d * NDIM + n0 + c4];
        Ts[(c4 + 0) * 65 + d] = v.x;
        Ts[(c4 + 1) * 65 + d] = v.y;
        Ts[(c4 + 2) * 65 + d] = v.z;
        Ts[(c4 + 3) * 65 + d] = v.w;
    }
    __syncthreads();

    uint2* __restrict__ dh = (uint2*)(which ? g_kh : g_qh);
    uint2* __restrict__ dl = (uint2*)(which ? g_kl : g_ql);
    for (int tt = tid; tt < 1024; tt += 256) {
        const int n  = tt >> 4;
        const int wp = tt & 15;
        const float f0 = Ts[n * 65 + 4 * wp + 0];
        const float f1 = Ts[n * 65 + 4 * wp + 1];
        const float f2 = Ts[n * 65 + 4 * wp + 2];
        const float f3 = Ts[n * 65 + 4 * wp + 3];
        uint32_t h0, l0, h1, l1;
        splitbf(f0, f1, h0, l0);
        splitbf(f2, f3, h1, l1);
        const size_t di = ((size_t)bh * NDIM + n0 + n) * 16 + wp;
        dh[di] = make_uint2(h0, h1);
        dl[di] = make_uint2(l0, l1);
    }
}

// ---------------------------------------------------------------------------
__global__ __launch_bounds__(256) void conv_v_kernel()
{
    const size_t idx = (size_t)blockIdx.x * 256 + threadIdx.x;  // float4 index
    const float4 v = ((const float4*)g_v)[idx];
    uint32_t h0, l0, h1, l1;
    splitbf(v.x, v.y, h0, l0);
    splitbf(v.z, v.w, h1, l1);
    ((uint2*)g_vh)[idx] = make_uint2(h0, h1);
    ((uint2*)g_vl)[idx] = make_uint2(l0, l1);
}

// ---------------------------------------------------------------------------
// Kernel 2: flash attention with split-bf16 mma (UNCHANGED — proven 363us).
// ---------------------------------------------------------------------------
#define ROWW 36
#define ARR  (64 * ROWW)
#define ATTN_SMEM_WORDS (6 * ARR)

__global__ __launch_bounds__(128) void attn_mma_kernel(float* __restrict__ out)
{
    extern __shared__ uint32_t sw[];
    uint32_t* qsh = sw;
    uint32_t* qsl = sw + ARR;
    uint32_t* ksh = sw + 2 * ARR;
    uint32_t* ksl = sw + 3 * ARR;
    uint32_t* vsh = sw + 4 * ARR;
    uint32_t* vsl = sw + 5 * ARR;

    const int bh = blockIdx.y;
    const int i0 = blockIdx.x * 64;

    const int tid  = threadIdx.x;
    const int lane = tid & 31;
    const int warp = tid >> 5;
    const int g    = lane >> 2;
    const int t    = lane & 3;

    {
        const uint4* qh = (const uint4*)(g_qh + ((size_t)bh * NDIM + i0) * DHEAD);
        const uint4* ql = (const uint4*)(g_ql + ((size_t)bh * NDIM + i0) * DHEAD);
        for (int kk = tid; kk < 512; kk += 128) {
            const int r = kk >> 3, c = kk & 7;
            *(uint4*)&qsh[r * ROWW + c * 4] = qh[r * 8 + c];
            *(uint4*)&qsl[r * ROWW + c * 4] = ql[r * 8 + c];
        }
    }
    __syncthreads();

    uint32_t Ah[4][4], Al[4][4];
    {
        const int qr = warp * 16 + g;
#pragma unroll
        for (int ks = 0; ks < 4; ks++) {
            Ah[ks][0] = qsh[qr * ROWW + 8 * ks + t];
            Ah[ks][1] = qsh[(qr + 8) * ROWW + 8 * ks + t];
            Ah[ks][2] = qsh[qr * ROWW + 8 * ks + t + 4];
            Ah[ks][3] = qsh[(qr + 8) * ROWW + 8 * ks + t + 4];
            Al[ks][0] = qsl[qr * ROWW + 8 * ks + t];
            Al[ks][1] = qsl[(qr + 8) * ROWW + 8 * ks + t];
            Al[ks][2] = qsl[qr * ROWW + 8 * ks + t + 4];
            Al[ks][3] = qsl[(qr + 8) * ROWW + 8 * ks + t + 4];
        }
    }

    float m0 = -INFINITY, m1 = -INFINITY, l0 = 0.f, l1 = 0.f;
    float O[8][4];
#pragma unroll
    for (int nt = 0; nt < 8; nt++)
#pragma unroll
        for (int c = 0; c < 4; c++) O[nt][c] = 0.f;

    for (int jt = 0; jt < NDIM / 64; jt++) {
        const int j0 = jt * 64;
        {
            const uint4* kh = (const uint4*)(g_kh + ((size_t)bh * NDIM + j0) * DHEAD);
            const uint4* kl = (const uint4*)(g_kl + ((size_t)bh * NDIM + j0) * DHEAD);
            const uint4* vh = (const uint4*)(g_vh + (size_t)bh * DHEAD * NDIM + j0);
            const uint4* vl = (const uint4*)(g_vl + (size_t)bh * DHEAD * NDIM + j0);
            for (int kk = tid; kk < 512; kk += 128) {
                const int r = kk >> 3, c = kk & 7;
                *(uint4*)&ksh[r * ROWW + c * 4] = kh[r * 8 + c];
                *(uint4*)&ksl[r * ROWW + c * 4] = kl[r * 8 + c];
                *(uint4*)&vsh[r * ROWW + c * 4] = vh[r * 128 + c];
                *(uint4*)&vsl[r * ROWW + c * 4] = vl[r * 128 + c];
            }
        }
        __syncthreads();

        float S[8][4];
#pragma unroll
        for (int nt = 0; nt < 8; nt++)
#pragma unroll
            for (int c = 0; c < 4; c++) S[nt][c] = 0.f;

#pragma unroll
        for (int nt = 0; nt < 8; nt++) {
            const int kr = (8 * nt + g) * ROWW;
#pragma unroll
            for (int ks = 0; ks < 4; ks++) {
                const uint32_t b0h = ksh[kr + 8 * ks + t];
                const uint32_t b1h = ksh[kr + 8 * ks + t + 4];
                const uint32_t b0l = ksl[kr + 8 * ks + t];
                const uint32_t b1l = ksl[kr + 8 * ks + t + 4];
                MMA_BF16(S[nt], Ah[ks], b0h, b1h);
                MMA_BF16(S[nt], Ah[ks], b0l, b1l);
                MMA_BF16(S[nt], Al[ks], b0h, b1h);
            }
        }

        float mx0 = S[0][0], mx1 = S[0][2];
#pragma unroll
        for (int nt = 0; nt < 8; nt++) {
            mx0 = fmaxf(mx0, fmaxf(S[nt][0], S[nt][1]));
            mx1 = fmaxf(mx1, fmaxf(S[nt][2], S[nt][3]));
        }
        mx0 = fmaxf(mx0, __shfl_xor_sync(0xffffffffu, mx0, 1));
        mx0 = fmaxf(mx0, __shfl_xor_sync(0xffffffffu, mx0, 2));
        mx1 = fmaxf(mx1, __shfl_xor_sync(0xffffffffu, mx1, 1));
        mx1 = fmaxf(mx1, __shfl_xor_sync(0xffffffffu, mx1, 2));

        const float mn0 = fmaxf(m0, mx0);
        const float mn1 = fmaxf(m1, mx1);
        const float al0 = __expf(m0 - mn0);
        const float al1 = __expf(m1 - mn1);
        m0 = mn0; m1 = mn1;

        float rs0 = 0.f, rs1 = 0.f;
#pragma unroll
        for (int nt = 0; nt < 8; nt++) {
            S[nt][0] = __expf(S[nt][0] - mn0); rs0 += S[nt][0];
            S[nt][1] = __expf(S[nt][1] - mn0); rs0 += S[nt][1];
            S[nt][2] = __expf(S[nt][2] - mn1); rs1 += S[nt][2];
            S[nt][3] = __expf(S[nt][3] - mn1); rs1 += S[nt][3];
        }
        rs0 += __shfl_xor_sync(0xffffffffu, rs0, 1);
        rs0 += __shfl_xor_sync(0xffffffffu, rs0, 2);
        rs1 += __shfl_xor_sync(0xffffffffu, rs1, 1);
        rs1 += __shfl_xor_sync(0xffffffffu, rs1, 2);
        l0 = l0 * al0 + rs0;
        l1 = l1 * al1 + rs1;

#pragma unroll
        for (int nt = 0; nt < 8; nt++) {
            O[nt][0] *= al0; O[nt][1] *= al0;
            O[nt][2] *= al1; O[nt][3] *= al1;
        }

#pragma unroll
        for (int kk = 0; kk < 4; kk++) {
            uint32_t Ph[4], Pl[4];
            splitbf(S[2 * kk][0],     S[2 * kk][1],     Ph[0], Pl[0]);
            splitbf(S[2 * kk][2],     S[2 * kk][3],     Ph[1], Pl[1]);
            splitbf(S[2 * kk + 1][0], S[2 * kk + 1][1], Ph[2], Pl[2]);
            splitbf(S[2 * kk + 1][2], S[2 * kk + 1][3], Ph[3], Pl[3]);
#pragma unroll
            for (int nt = 0; nt < 8; nt++) {
                const int vr = (8 * nt + g) * ROWW;
                const uint32_t b0h = vsh[vr + 8 * kk + t];
                const uint32_t b1h = vsh[vr + 8 * kk + t + 4];
                const uint32_t b0l = vsl[vr + 8 * kk + t];
                const uint32_t b1l = vsl[vr + 8 * kk + t + 4];
                MMA_BF16(O[nt], Ph, b0h, b1h);
                MMA_BF16(O[nt], Ph, b0l, b1l);
                MMA_BF16(O[nt], Pl, b0h, b1h);
            }
        }
        __syncthreads();
    }

    const float inv0 = 1.0f / l0;
    const float inv1 = 1.0f / l1;
    const int i = i0 + warp * 16 + g;
    float* __restrict__ op0 = out + ((size_t)bh * NDIM + i) * DHEAD;
    float* __restrict__ op1 = out + ((size_t)bh * NDIM + i + 8) * DHEAD;
#pragma unroll
    for (int nt = 0; nt < 8; nt++) {
        const int dd = 8 * nt + 2 * t;
        *(float2*)&op0[dd] = make_float2(O[nt][0] * inv0, O[nt][1] * inv0);
        *(float2*)&op1[dd] = make_float2(O[nt][2] * inv1, O[nt][3] * inv1);
    }
}

// ---------------------------------------------------------------------------
extern "C" void kernel_launch(void* const* d_in, const int* in_sizes, int n_in,
                              void* d_out, int out_size)
{
    const float* x     = (const float*)d_in[0];
    const float* Wq    = (const float*)d_in[1];
    const float* bq    = (const float*)d_in[2];
    const float* Wk    = (const float*)d_in[3];
    const float* bk    = (const float*)d_in[4];
    const float* Wv    = (const float*)d_in[5];
    const float* bv    = (const float*)d_in[6];
    const float* rel_h = (const float*)d_in[7];
    const float* rel_w = (const float*)d_in[8];
    float* out = (float*)d_out;

    cudaFuncSetAttribute(attn_mma_kernel,
                         cudaFuncAttributeMaxDynamicSharedMemorySize,
                         ATTN_SMEM_WORDS * 4);

    // 1) QKV projections (tensor-core split-bf16)
    dim3 g1(NDIM / 128, CDIM / 128, 3 * BDIM);
    qkv_gemm_mma_kernel<<<g1, 256>>>(x, Wq, bq, Wk, bk, Wv, bv, rel_h, rel_w);

    // 2) split-bf16 conversions
    dim3 gc(NDIM / 64, NBH, 2);
    conv_qk_t_kernel<<<gc, 256>>>();
    conv_v_kernel<<<(NBH * DHEAD * NDIM / 4) / 256, 256>>>();

    // 3) tensor-core flash attention
    dim3 g2(NDIM / 64, NBH);
    attn_mma_kernel<<<g2, 128, ATTN_SMEM_WORDS * 4>>>(out);
}

// round 14
// speedup vs baseline: 2.2080x; 1.0569x over previous
#include <cstdint>
#include <stdint.h>
#include <cuda_runtime.h>
#include <cuda_bf16.h>
#include <math.h>

// Problem constants
#define BDIM 16
#define CDIM 512
#define NDIM 1024
#define NHEADS 8
#define DHEAD 64
#define QSCALE 0.125f
#define NBH (BDIM * NHEADS)

// fp32 scratch (q, k only — v goes straight to split-bf16 in the GEMM epilogue)
__device__ float g_q[BDIM * CDIM * NDIM];
__device__ float g_k[BDIM * CDIM * NDIM];

// split-bf16 operand arrays for the mma attention
__device__ __nv_bfloat16 g_qh[NBH * NDIM * DHEAD];  // [bh][i][d]
__device__ __nv_bfloat16 g_ql[NBH * NDIM * DHEAD];
__device__ __nv_bfloat16 g_kh[NBH * NDIM * DHEAD];  // [bh][j][d]
__device__ __nv_bfloat16 g_kl[NBH * NDIM * DHEAD];
__device__ __nv_bfloat16 g_vh[NBH * DHEAD * NDIM];  // [bh][d][j]
__device__ __nv_bfloat16 g_vl[NBH * DHEAD * NDIM];

// ---------------------------------------------------------------------------
__device__ __forceinline__ void splitbf(float a, float b,
                                        uint32_t& hi, uint32_t& lo)
{
    __nv_bfloat16 ah = __float2bfloat16_rn(a);
    __nv_bfloat16 bh = __float2bfloat16_rn(b);
    __nv_bfloat16 al = __float2bfloat16_rn(a - __bfloat162float(ah));
    __nv_bfloat16 bl = __float2bfloat16_rn(b - __bfloat162float(bh));
    __nv_bfloat162 h; h.x = ah; h.y = bh;
    __nv_bfloat162 l; l.x = al; l.y = bl;
    hi = *(uint32_t*)&h;
    lo = *(uint32_t*)&l;
}

#define MMA_BF16(C, A, b0, b1)                                               \
    asm volatile(                                                            \
        "mma.sync.aligned.m16n8k16.row.col.f32.bf16.bf16.f32 "               \
        "{%0,%1,%2,%3},{%4,%5,%6,%7},{%8,%9},{%0,%1,%2,%3};\n"               \
        : "+f"((C)[0]), "+f"((C)[1]), "+f"((C)[2]), "+f"((C)[3])             \
        : "r"((A)[0]), "r"((A)[1]), "r"((A)[2]), "r"((A)[3]),                \
          "r"(b0), "r"(b1))

__device__ __forceinline__ void cpa16(uint32_t smem_addr, const void* gptr)
{
    asm volatile("cp.async.cg.shared.global [%0], [%1], 16;\n"
                 :: "r"(smem_addr), "l"(gptr));
}
#define CP_COMMIT() asm volatile("cp.async.commit_group;\n" ::: "memory")
#define CP_WAIT1()  asm volatile("cp.async.wait_group 1;\n" ::: "memory")
#define CP_WAIT0()  asm volatile("cp.async.wait_group 0;\n" ::: "memory")

// ---------------------------------------------------------------------------
// Kernel 1: QKV projection via split-bf16 tensor cores (proven R11 version).
// NEW: mat==2 (V) writes split-bf16 g_vh/g_vl directly (n-pair packing matches
// the acc fragment); fp32 scratch skipped for V entirely.
// ---------------------------------------------------------------------------
#define KC 32
#define GROWW 20

__global__ __launch_bounds__(256) void qkv_gemm_mma_kernel(
    const float* __restrict__ x,
    const float* __restrict__ Wq, const float* __restrict__ bq,
    const float* __restrict__ Wk, const float* __restrict__ bk,
    const float* __restrict__ Wv, const float* __restrict__ bv,
    const float* __restrict__ rel_h, const float* __restrict__ rel_w)
{
    const int mat = blockIdx.z >> 4;   // 0=q, 1=k, 2=v
    const int b   = blockIdx.z & 15;

    const float* __restrict__ W    = (mat == 0) ? Wq : (mat == 1) ? Wk : Wv;
    const float* __restrict__ bias = (mat == 0) ? bq : (mat == 1) ? bk : bv;

    const int o0 = blockIdx.y * 128;
    const int n0 = blockIdx.x * 128;

    __shared__ uint32_t Wh[128 * GROWW], Wl[128 * GROWW];
    __shared__ uint32_t Xh[128 * GROWW], Xl[128 * GROWW];

    const int tid  = threadIdx.x;
    const int lane = tid & 31;
    const int warp = tid >> 5;
    const int g    = lane >> 2;
    const int t    = lane & 3;
    const int wm   = (warp >> 2) * 64;
    const int wn   = (warp & 3) * 32;

    float acc[4][4][4];
#pragma unroll
    for (int mt = 0; mt < 4; mt++)
#pragma unroll
        for (int nt = 0; nt < 4; nt++)
#pragma unroll
            for (int c = 0; c < 4; c++) acc[mt][nt][c] = 0.f;

    const float* __restrict__ xb = x + (size_t)b * CDIM * NDIM;

    const int lo_w = tid >> 1;
    const int lc_w = (tid & 1) * 16;
    const int lc_x = 2 * (tid & 15);
    const int ln_x = ((tid >> 4) & 15) * 4;

    float4 pw0 = *(const float4*)&W[(size_t)(o0 + lo_w) * CDIM + lc_w];
    float4 pw1 = *(const float4*)&W[(size_t)(o0 + lo_w) * CDIM + lc_w + 4];
    float4 pw2 = *(const float4*)&W[(size_t)(o0 + lo_w) * CDIM + lc_w + 8];
    float4 pw3 = *(const float4*)&W[(size_t)(o0 + lo_w) * CDIM + lc_w + 12];
    float4 px00 = *(const float4*)&xb[(size_t)lc_x * NDIM + n0 + ln_x];
    float4 px01 = *(const float4*)&xb[(size_t)(lc_x + 1) * NDIM + n0 + ln_x];
    float4 px10 = *(const float4*)&xb[(size_t)lc_x * NDIM + n0 + ln_x + 64];
    float4 px11 = *(const float4*)&xb[(size_t)(lc_x + 1) * NDIM + n0 + ln_x + 64];

    for (int k0 = 0; k0 < CDIM; k0 += KC) {
        __syncthreads();
        {
            uint32_t h0, h1, h2, h3, h4, h5, h6, h7;
            uint32_t l0, l1, l2, l3, l4, l5, l6, l7;
            splitbf(pw0.x, pw0.y, h0, l0); splitbf(pw0.z, pw0.w, h1, l1);
            splitbf(pw1.x, pw1.y, h2, l2); splitbf(pw1.z, pw1.w, h3, l3);
            splitbf(pw2.x, pw2.y, h4, l4); splitbf(pw2.z, pw2.w, h5, l5);
            splitbf(pw3.x, pw3.y, h6, l6); splitbf(pw3.z, pw3.w, h7, l7);
            const int wb = lo_w * GROWW + lc_w / 2;
            *(uint4*)&Wh[wb]     = make_uint4(h0, h1, h2, h3);
            *(uint4*)&Wh[wb + 4] = make_uint4(h4, h5, h6, h7);
            *(uint4*)&Wl[wb]     = make_uint4(l0, l1, l2, l3);
            *(uint4*)&Wl[wb + 4] = make_uint4(l4, l5, l6, l7);
        }
        {
            const int cp = tid & 15;
            uint32_t hi, lo;
            splitbf(px00.x, px01.x, hi, lo);
            Xh[(ln_x + 0) * GROWW + cp] = hi; Xl[(ln_x + 0) * GROWW + cp] = lo;
            splitbf(px00.y, px01.y, hi, lo);
            Xh[(ln_x + 1) * GROWW + cp] = hi; Xl[(ln_x + 1) * GROWW + cp] = lo;
            splitbf(px00.z, px01.z, hi, lo);
            Xh[(ln_x + 2) * GROWW + cp] = hi; Xl[(ln_x + 2) * GROWW + cp] = lo;
            splitbf(px00.w, px01.w, hi, lo);
            Xh[(ln_x + 3) * GROWW + cp] = hi; Xl[(ln_x + 3) * GROWW + cp] = lo;
            splitbf(px10.x, px11.x, hi, lo);
            Xh[(ln_x + 64) * GROWW + cp] = hi; Xl[(ln_x + 64) * GROWW + cp] = lo;
            splitbf(px10.y, px11.y, hi, lo);
            Xh[(ln_x + 65) * GROWW + cp] = hi; Xl[(ln_x + 65) * GROWW + cp] = lo;
            splitbf(px10.z, px11.z, hi, lo);
            Xh[(ln_x + 66) * GROWW + cp] = hi; Xl[(ln_x + 66) * GROWW + cp] = lo;
            splitbf(px10.w, px11.w, hi, lo);
            Xh[(ln_x + 67) * GROWW + cp] = hi; Xl[(ln_x + 67) * GROWW + cp] = lo;
        }
        __syncthreads();

        if (k0 + KC < CDIM) {
            const int kn = k0 + KC;
            pw0 = *(const float4*)&W[(size_t)(o0 + lo_w) * CDIM + kn + lc_w];
            pw1 = *(const float4*)&W[(size_t)(o0 + lo_w) * CDIM + kn + lc_w + 4];
            pw2 = *(const float4*)&W[(size_t)(o0 + lo_w) * CDIM + kn + lc_w + 8];
            pw3 = *(const float4*)&W[(size_t)(o0 + lo_w) * CDIM + kn + lc_w + 12];
            px00 = *(const float4*)&xb[(size_t)(kn + lc_x) * NDIM + n0 + ln_x];
            px01 = *(const float4*)&xb[(size_t)(kn + lc_x + 1) * NDIM + n0 + ln_x];
            px10 = *(const float4*)&xb[(size_t)(kn + lc_x) * NDIM + n0 + ln_x + 64];
            px11 = *(const float4*)&xb[(size_t)(kn + lc_x + 1) * NDIM + n0 + ln_x + 64];
        }

#pragma unroll
        for (int ks = 0; ks < 2; ks++) {
            uint32_t Ah[4][4], Al[4][4];
#pragma unroll
            for (int mt = 0; mt < 4; mt++) {
                const int r0 = (wm + mt * 16 + g) * GROWW + ks * 8 + t;
                const int r1 = (wm + mt * 16 + 8 + g) * GROWW + ks * 8 + t;
                Ah[mt][0] = Wh[r0]; Ah[mt][1] = Wh[r1];
                Ah[mt][2] = Wh[r0 + 4]; Ah[mt][3] = Wh[r1 + 4];
                Al[mt][0] = Wl[r0]; Al[mt][1] = Wl[r1];
                Al[mt][2] = Wl[r0 + 4]; Al[mt][3] = Wl[r1 + 4];
            }
            uint32_t Bh[4][2], Bl[4][2];
#pragma unroll
            for (int nt = 0; nt < 4; nt++) {
                const int rr = (wn + nt * 8 + g) * GROWW + ks * 8 + t;
                Bh[nt][0] = Xh[rr]; Bh[nt][1] = Xh[rr + 4];
                Bl[nt][0] = Xl[rr]; Bl[nt][1] = Xl[rr + 4];
            }
#pragma unroll
            for (int mt = 0; mt < 4; mt++)
#pragma unroll
                for (int nt = 0; nt < 4; nt++) {
                    MMA_BF16(acc[mt][nt], Ah[mt], Bh[nt][0], Bh[nt][1]);
                    MMA_BF16(acc[mt][nt], Ah[mt], Bl[nt][0], Bl[nt][1]);
                    MMA_BF16(acc[mt][nt], Al[mt], Bh[nt][0], Bh[nt][1]);
                }
        }
    }

    // ---- epilogue ----
    if (mat == 2) {
        // V: write split-bf16 [bh][d][j] directly (word = n-pair)
        uint32_t* __restrict__ vh = (uint32_t*)g_vh;
        uint32_t* __restrict__ vl = (uint32_t*)g_vl;
        const size_t vbase = (size_t)b * CDIM * (NDIM / 2);
#pragma unroll
        for (int mt = 0; mt < 4; mt++) {
            const int o_a = o0 + wm + mt * 16 + g;
            const int o_b = o_a + 8;
            const float bia = bias[o_a];
            const float bib = bias[o_b];
#pragma unroll
            for (int nt = 0; nt < 4; nt++) {
                const int n = n0 + wn + nt * 8 + 2 * t;
                uint32_t h, l;
                splitbf(acc[mt][nt][0] + bia, acc[mt][nt][1] + bia, h, l);
                size_t wa = vbase + (size_t)o_a * (NDIM / 2) + (n >> 1);
                vh[wa] = h; vl[wa] = l;
                splitbf(acc[mt][nt][2] + bib, acc[mt][nt][3] + bib, h, l);
                wa = vbase + (size_t)o_b * (NDIM / 2) + (n >> 1);
                vh[wa] = h; vl[wa] = l;
            }
        }
    } else {
        float* __restrict__ out = (mat == 0) ? g_q : g_k;
        const size_t obase = (size_t)b * CDIM * NDIM;
#pragma unroll
        for (int mt = 0; mt < 4; mt++) {
            const int o_a = o0 + wm + mt * 16 + g;
            const int o_b = o_a + 8;
            const float bia = bias[o_a];
            const float bib = bias[o_b];
            const int dda = o_a & 63;
            const int ddb = o_b & 63;
#pragma unroll
            for (int nt = 0; nt < 4; nt++) {
                const int n = n0 + wn + nt * 8 + 2 * t;
                float v0 = acc[mt][nt][0] + bia;
                float v1 = acc[mt][nt][1] + bia;
                float v2 = acc[mt][nt][2] + bib;
                float v3 = acc[mt][nt][3] + bib;
                if (mat == 0) {
                    v0 *= QSCALE; v1 *= QSCALE; v2 *= QSCALE; v3 *= QSCALE;
                } else {
                    v0 += rel_h[dda * 32 + (n >> 5)] + rel_w[dda * 32 + (n & 31)];
                    v1 += rel_h[dda * 32 + ((n + 1) >> 5)] + rel_w[dda * 32 + ((n + 1) & 31)];
                    v2 += rel_h[ddb * 32 + (n >> 5)] + rel_w[ddb * 32 + (n & 31)];
                    v3 += rel_h[ddb * 32 + ((n + 1) >> 5)] + rel_w[ddb * 32 + ((n + 1) & 31)];
                }
                *(float2*)&out[obase + (size_t)o_a * NDIM + n] = make_float2(v0, v1);
                *(float2*)&out[obase + (size_t)o_b * NDIM + n] = make_float2(v2, v3);
            }
        }
    }
}

// ---------------------------------------------------------------------------
// Conversion: q,k fp32 [bh][d][n] -> split-bf16 [bh][i][d] (smem transpose).
// ---------------------------------------------------------------------------
__global__ __launch_bounds__(256) void conv_qk_t_kernel()
{
    const int n0    = blockIdx.x * 64;
    const int bh    = blockIdx.y;
    const int which = blockIdx.z;

    const float* __restrict__ src =
        (which ? g_k : g_q) + (size_t)bh * DHEAD * NDIM;

    __shared__ float Ts[64 * 65];
    const int tid = threadIdx.x;

    for (int tt = tid; tt < 1024; tt += 256) {
        const int d  = tt >> 4;
        const int c4 = (tt & 15) * 4;
        const float4 v = *(const float4*)&src[(size_t)d * NDIM + n0 + c4];
        Ts[(c4 + 0) * 65 + d] = v.x;
        Ts[(c4 + 1) * 65 + d] = v.y;
        Ts[(c4 + 2) * 65 + d] = v.z;
        Ts[(c4 + 3) * 65 + d] = v.w;
    }
    __syncthreads();

    uint2* __restrict__ dh = (uint2*)(which ? g_kh : g_qh);
    uint2* __restrict__ dl = (uint2*)(which ? g_kl : g_ql);
    for (int tt = tid; tt < 1024; tt += 256) {
        const int n  = tt >> 4;
        const int wp = tt & 15;
        const float f0 = Ts[n * 65 + 4 * wp + 0];
        const float f1 = Ts[n * 65 + 4 * wp + 1];
        const float f2 = Ts[n * 65 + 4 * wp + 2];
        const float f3 = Ts[n * 65 + 4 * wp + 3];
        uint32_t h0, l0, h1, l1;
        splitbf(f0, f1, h0, l0);
        splitbf(f2, f3, h1, l1);
        const size_t di = ((size_t)bh * NDIM + n0 + n) * 16 + wp;
        dh[di] = make_uint2(h0, h1);
        dl[di] = make_uint2(l0, l1);
    }
}

// ---------------------------------------------------------------------------
// Kernel 2: flash attention, split-bf16 mma + cp.async double-buffered K/V.
// smem: qs hi/lo (2*ARR) + two K/V buffers (4*ARR each) = 10*ARR = 92 KB.
// Pipeline: tiles jt and jt+1 in flight; wait_group(1) -> tile jt ready.
// ---------------------------------------------------------------------------
#define ROWW 36
#define ARR  (64 * ROWW)
#define ATTN_SMEM_WORDS (10 * ARR)   // 23040 words = 92160 B

__global__ __launch_bounds__(128) void attn_mma_kernel(float* __restrict__ out)
{
    extern __shared__ uint32_t sw[];
    uint32_t* qsh = sw;
    uint32_t* qsl = sw + ARR;
    // buffers: base 2*ARR + buf*4*ARR; order ksh, ksl, vsh, vsl
    const uint32_t swb = (uint32_t)__cvta_generic_to_shared(sw);

    const int bh = blockIdx.y;
    const int i0 = blockIdx.x * 64;

    const int tid  = threadIdx.x;
    const int lane = tid & 31;
    const int warp = tid >> 5;
    const int g    = lane >> 2;
    const int t    = lane & 3;

    const uint4* khb = (const uint4*)(g_kh + (size_t)bh * NDIM * DHEAD);
    const uint4* klb = (const uint4*)(g_kl + (size_t)bh * NDIM * DHEAD);
    const uint4* vhb = (const uint4*)(g_vh + (size_t)bh * DHEAD * NDIM);
    const uint4* vlb = (const uint4*)(g_vl + (size_t)bh * DHEAD * NDIM);

    // issue tiles 0 and 1 (each: K rows j0..j0+63 x 8 uint4; V rows d x 8 uint4)
#pragma unroll
    for (int pb = 0; pb < 2; pb++) {
        const int j0 = pb * 64;
        const uint32_t base = swb + (2 * ARR + pb * 4 * ARR) * 4;
        for (int kk = tid; kk < 512; kk += 128) {
            const int r = kk >> 3, c = kk & 7;
            const uint32_t so = (uint32_t)(r * ROWW + c * 4) * 4;
            cpa16(base + so,               khb + (size_t)(j0 + r) * 8 + c);
            cpa16(base + ARR * 4 + so,     klb + (size_t)(j0 + r) * 8 + c);
            cpa16(base + 2 * ARR * 4 + so, vhb + (size_t)r * 128 + (j0 >> 3) + c);
            cpa16(base + 3 * ARR * 4 + so, vlb + (size_t)r * 128 + (j0 >> 3) + c);
        }
        CP_COMMIT();
    }

    // load Q tile (normal LDG/STS, overlaps the async copies)
    {
        const uint4* qh = (const uint4*)(g_qh + ((size_t)bh * NDIM + i0) * DHEAD);
        const uint4* ql = (const uint4*)(g_ql + ((size_t)bh * NDIM + i0) * DHEAD);
        for (int kk = tid; kk < 512; kk += 128) {
            const int r = kk >> 3, c = kk & 7;
            *(uint4*)&qsh[r * ROWW + c * 4] = qh[r * 8 + c];
            *(uint4*)&qsl[r * ROWW + c * 4] = ql[r * 8 + c];
        }
    }
    __syncthreads();

    uint32_t Ah[4][4], Al[4][4];
    {
        const int qr = warp * 16 + g;
#pragma unroll
        for (int ks = 0; ks < 4; ks++) {
            Ah[ks][0] = qsh[qr * ROWW + 8 * ks + t];
            Ah[ks][1] = qsh[(qr + 8) * ROWW + 8 * ks + t];
            Ah[ks][2] = qsh[qr * ROWW + 8 * ks + t + 4];
            Ah[ks][3] = qsh[(qr + 8) * ROWW + 8 * ks + t + 4];
            Al[ks][0] = qsl[qr * ROWW + 8 * ks + t];
            Al[ks][1] = qsl[(qr + 8) * ROWW + 8 * ks + t];
            Al[ks][2] = qsl[qr * ROWW + 8 * ks + t + 4];
            Al[ks][3] = qsl[(qr + 8) * ROWW + 8 * ks + t + 4];
        }
    }

    float m0 = -INFINITY, m1 = -INFINITY, l0 = 0.f, l1 = 0.f;
    float O[8][4];
#pragma unroll
    for (int nt = 0; nt < 8; nt++)
#pragma unroll
        for (int c = 0; c < 4; c++) O[nt][c] = 0.f;

#pragma unroll 1
    for (int jt = 0; jt < NDIM / 64; jt++) {
        // tile jt ready (tile jt+1 may still be in flight)
        if (jt < NDIM / 64 - 1) { CP_WAIT1(); } else { CP_WAIT0(); }
        __syncthreads();

        const uint32_t* ksh = sw + 2 * ARR + (jt & 1) * 4 * ARR;
        const uint32_t* ksl = ksh + ARR;
        const uint32_t* vsh = ksh + 2 * ARR;
        const uint32_t* vsl = ksh + 3 * ARR;

        float S[8][4];
#pragma unroll
        for (int nt = 0; nt < 8; nt++)
#pragma unroll
            for (int c = 0; c < 4; c++) S[nt][c] = 0.f;

#pragma unroll
        for (int nt = 0; nt < 8; nt++) {
            const int kr = (8 * nt + g) * ROWW;
#pragma unroll
            for (int ks = 0; ks < 4; ks++) {
                const uint32_t b0h = ksh[kr + 8 * ks + t];
                const uint32_t b1h = ksh[kr + 8 * ks + t + 4];
                const uint32_t b0l = ksl[kr + 8 * ks + t];
                const uint32_t b1l = ksl[kr + 8 * ks + t + 4];
                MMA_BF16(S[nt], Ah[ks], b0h, b1h);
                MMA_BF16(S[nt], Ah[ks], b0l, b1l);
                MMA_BF16(S[nt], Al[ks], b0h, b1h);
            }
        }

        float mx0 = S[0][0], mx1 = S[0][2];
#pragma unroll
        for (int nt = 0; nt < 8; nt++) {
            mx0 = fmaxf(mx0, fmaxf(S[nt][0], S[nt][1]));
            mx1 = fmaxf(mx1, fmaxf(S[nt][2], S[nt][3]));
        }
        mx0 = fmaxf(mx0, __shfl_xor_sync(0xffffffffu, mx0, 1));
        mx0 = fmaxf(mx0, __shfl_xor_sync(0xffffffffu, mx0, 2));
        mx1 = fmaxf(mx1, __shfl_xor_sync(0xffffffffu, mx1, 1));
        mx1 = fmaxf(mx1, __shfl_xor_sync(0xffffffffu, mx1, 2));

        const float mn0 = fmaxf(m0, mx0);
        const float mn1 = fmaxf(m1, mx1);
        const float al0 = __expf(m0 - mn0);
        const float al1 = __expf(m1 - mn1);
        m0 = mn0; m1 = mn1;

        float rs0 = 0.f, rs1 = 0.f;
#pragma unroll
        for (int nt = 0; nt < 8; nt++) {
            S[nt][0] = __expf(S[nt][0] - mn0); rs0 += S[nt][0];
            S[nt][1] = __expf(S[nt][1] - mn0); rs0 += S[nt][1];
            S[nt][2] = __expf(S[nt][2] - mn1); rs1 += S[nt][2];
            S[nt][3] = __expf(S[nt][3] - mn1); rs1 += S[nt][3];
        }
        rs0 += __shfl_xor_sync(0xffffffffu, rs0, 1);
        rs0 += __shfl_xor_sync(0xffffffffu, rs0, 2);
        rs1 += __shfl_xor_sync(0xffffffffu, rs1, 1);
        rs1 += __shfl_xor_sync(0xffffffffu, rs1, 2);
        l0 = l0 * al0 + rs0;
        l1 = l1 * al1 + rs1;

#pragma unroll
        for (int nt = 0; nt < 8; nt++) {
            O[nt][0] *= al0; O[nt][1] *= al0;
            O[nt][2] *= al1; O[nt][3] *= al1;
        }

#pragma unroll
        for (int kk = 0; kk < 4; kk++) {
            uint32_t Ph[4], Pl[4];
            splitbf(S[2 * kk][0],     S[2 * kk][1],     Ph[0], Pl[0]);
            splitbf(S[2 * kk][2],     S[2 * kk][3],     Ph[1], Pl[1]);
            splitbf(S[2 * kk + 1][0], S[2 * kk + 1][1], Ph[2], Pl[2]);
            splitbf(S[2 * kk + 1][2], S[2 * kk + 1][3], Ph[3], Pl[3]);
#pragma unroll
            for (int nt = 0; nt < 8; nt++) {
                const int vr = (8 * nt + g) * ROWW;
                const uint32_t b0h = vsh[vr + 8 * kk + t];
                const uint32_t b1h = vsh[vr + 8 * kk + t + 4];
                const uint32_t b0l = vsl[vr + 8 * kk + t];
                const uint32_t b1l = vsl[vr + 8 * kk + t + 4];
                MMA_BF16(O[nt], Ph, b0h, b1h);
                MMA_BF16(O[nt], Ph, b0l, b1l);
                MMA_BF16(O[nt], Pl, b0h, b1h);
            }
        }
        __syncthreads();   // all warps done reading buffer jt&1

        // prefetch tile jt+2 into the buffer just freed
        if (jt + 2 < NDIM / 64) {
            const int j0 = (jt + 2) * 64;
            const uint32_t base = swb + (2 * ARR + (jt & 1) * 4 * ARR) * 4;
            for (int kk = tid; kk < 512; kk += 128) {
                const int r = kk >> 3, c = kk & 7;
                const uint32_t so = (uint32_t)(r * ROWW + c * 4) * 4;
                cpa16(base + so,               khb + (size_t)(j0 + r) * 8 + c);
                cpa16(base + ARR * 4 + so,     klb + (size_t)(j0 + r) * 8 + c);
                cpa16(base + 2 * ARR * 4 + so, vhb + (size_t)r * 128 + (j0 >> 3) + c);
                cpa16(base + 3 * ARR * 4 + so, vlb + (size_t)r * 128 + (j0 >> 3) + c);
            }
            CP_COMMIT();
        }
    }

    const float inv0 = 1.0f / l0;
    const float inv1 = 1.0f / l1;
    const int i = i0 + warp * 16 + g;
    float* __restrict__ op0 = out + ((size_t)bh * NDIM + i) * DHEAD;
    float* __restrict__ op1 = out + ((size_t)bh * NDIM + i + 8) * DHEAD;
#pragma unroll
    for (int nt = 0; nt < 8; nt++) {
        const int dd = 8 * nt + 2 * t;
        *(float2*)&op0[dd] = make_float2(O[nt][0] * inv0, O[nt][1] * inv0);
        *(float2*)&op1[dd] = make_float2(O[nt][2] * inv1, O[nt][3] * inv1);
    }
}

// ---------------------------------------------------------------------------
extern "C" void kernel_launch(void* const* d_in, const int* in_sizes, int n_in,
                              void* d_out, int out_size)
{
    const float* x     = (const float*)d_in[0];
    const float* Wq    = (const float*)d_in[1];
    const float* bq    = (const float*)d_in[2];
    const float* Wk    = (const float*)d_in[3];
    const float* bk    = (const float*)d_in[4];
    const float* Wv    = (const float*)d_in[5];
    const float* bv    = (const float*)d_in[6];
    const float* rel_h = (const float*)d_in[7];
    const float* rel_w = (const float*)d_in[8];
    float* out = (float*)d_out;

    cudaFuncSetAttribute(attn_mma_kernel,
                         cudaFuncAttributeMaxDynamicSharedMemorySize,
                         ATTN_SMEM_WORDS * 4);

    // 1) QKV projections (V emits split-bf16 directly)
    dim3 g1(NDIM / 128, CDIM / 128, 3 * BDIM);
    qkv_gemm_mma_kernel<<<g1, 256>>>(x, Wq, bq, Wk, bk, Wv, bv, rel_h, rel_w);

    // 2) split-bf16 conversion for q, k only
    dim3 gc(NDIM / 64, NBH, 2);
    conv_qk_t_kernel<<<gc, 256>>>();

    // 3) tensor-core flash attention (double-buffered)
    dim3 g2(NDIM / 64, NBH);
    attn_mma_kernel<<<g2, 128, ATTN_SMEM_WORDS * 4>>>(out);
}

// round 15
// speedup vs baseline: 2.7185x; 1.2312x over previous
#include <cstdint>
#include <stdint.h>
#include <cuda_runtime.h>
#include <cuda_bf16.h>
#include <math.h>

// Problem constants
#define BDIM 16
#define CDIM 512
#define NDIM 1024
#define NHEADS 8
#define DHEAD 64
#define QSCALE 0.125f
#define NBH (BDIM * NHEADS)

// fp32 scratch (q, k only)
__device__ float g_q[BDIM * CDIM * NDIM];
__device__ float g_k[BDIM * CDIM * NDIM];

// pre-split GEMM operands
__device__ __nv_bfloat16 g_wh[3 * CDIM * CDIM];      // [mat][o][c-pair words]
__device__ __nv_bfloat16 g_wl[3 * CDIM * CDIM];
__device__ __nv_bfloat16 g_xh[BDIM * NDIM * CDIM];   // [b][n][c-pair words]
__device__ __nv_bfloat16 g_xl[BDIM * NDIM * CDIM];

// split-bf16 operands for attention
__device__ __nv_bfloat16 g_qh[NBH * NDIM * DHEAD];   // [bh][i][d]
__device__ __nv_bfloat16 g_ql[NBH * NDIM * DHEAD];
__device__ __nv_bfloat16 g_kh[NBH * NDIM * DHEAD];   // [bh][j][d]
__device__ __nv_bfloat16 g_kl[NBH * NDIM * DHEAD];
__device__ __nv_bfloat16 g_vh[NBH * DHEAD * NDIM];   // [bh][d][j]
__device__ __nv_bfloat16 g_vl[NBH * DHEAD * NDIM];

// ---------------------------------------------------------------------------
__device__ __forceinline__ void splitbf(float a, float b,
                                        uint32_t& hi, uint32_t& lo)
{
    __nv_bfloat16 ah = __float2bfloat16_rn(a);
    __nv_bfloat16 bh = __float2bfloat16_rn(b);
    __nv_bfloat16 al = __float2bfloat16_rn(a - __bfloat162float(ah));
    __nv_bfloat16 bl = __float2bfloat16_rn(b - __bfloat162float(bh));
    __nv_bfloat162 h; h.x = ah; h.y = bh;
    __nv_bfloat162 l; l.x = al; l.y = bl;
    hi = *(uint32_t*)&h;
    lo = *(uint32_t*)&l;
}

#define MMA_BF16(C, A, b0, b1)                                               \
    asm volatile(                                                            \
        "mma.sync.aligned.m16n8k16.row.col.f32.bf16.bf16.f32 "               \
        "{%0,%1,%2,%3},{%4,%5,%6,%7},{%8,%9},{%0,%1,%2,%3};\n"               \
        : "+f"((C)[0]), "+f"((C)[1]), "+f"((C)[2]), "+f"((C)[3])             \
        : "r"((A)[0]), "r"((A)[1]), "r"((A)[2]), "r"((A)[3]),                \
          "r"(b0), "r"(b1))

__device__ __forceinline__ void cpa16(uint32_t smem_addr, const void* gptr)
{
    asm volatile("cp.async.cg.shared.global [%0], [%1], 16;\n"
                 :: "r"(smem_addr), "l"(gptr));
}
#define CP_COMMIT() asm volatile("cp.async.commit_group;\n" ::: "memory")
#define CP_WAIT1()  asm volatile("cp.async.wait_group 1;\n" ::: "memory")
#define CP_WAIT0()  asm volatile("cp.async.wait_group 0;\n" ::: "memory")

// ---------------------------------------------------------------------------
// conv_w: W fp32 [o][c] -> split-bf16 c-pair words (sequential pairs).
// ---------------------------------------------------------------------------
__global__ __launch_bounds__(256) void conv_w_kernel(
    const float* __restrict__ Wq, const float* __restrict__ Wk,
    const float* __restrict__ Wv)
{
    const size_t idx = (size_t)blockIdx.x * 256 + threadIdx.x;  // uint2 index
    const int mat = (int)(idx / (CDIM * CDIM / 4));
    const size_t r = idx % (CDIM * CDIM / 4);                   // float4 index
    const float* __restrict__ W = (mat == 0) ? Wq : (mat == 1) ? Wk : Wv;
    const float4 v = ((const float4*)W)[r];
    uint32_t h0, l0, h1, l1;
    splitbf(v.x, v.y, h0, l0);
    splitbf(v.z, v.w, h1, l1);
    ((uint2*)g_wh)[idx] = make_uint2(h0, h1);
    ((uint2*)g_wl)[idx] = make_uint2(l0, l1);
}

// ---------------------------------------------------------------------------
// conv_x: x fp32 [b][c][n] -> split-bf16 [b][n][c-pair words] (smem transpose).
// ---------------------------------------------------------------------------
__global__ __launch_bounds__(256) void conv_x_kernel(const float* __restrict__ x)
{
    const int n0 = blockIdx.x * 64;
    const int c0 = blockIdx.y * 64;
    const int b  = blockIdx.z;

    const float* __restrict__ src = x + ((size_t)b * CDIM + c0) * NDIM;

    __shared__ float Ts[64 * 65];   // [n][c]
    const int tid = threadIdx.x;

    for (int tt = tid; tt < 1024; tt += 256) {
        const int c  = tt >> 4;
        const int n4 = (tt & 15) * 4;
        const float4 v = *(const float4*)&src[(size_t)c * NDIM + n0 + n4];
        Ts[(n4 + 0) * 65 + c] = v.x;
        Ts[(n4 + 1) * 65 + c] = v.y;
        Ts[(n4 + 2) * 65 + c] = v.z;
        Ts[(n4 + 3) * 65 + c] = v.w;
    }
    __syncthreads();

    uint2* __restrict__ dh = (uint2*)g_xh;
    uint2* __restrict__ dl = (uint2*)g_xl;
    for (int tt = tid; tt < 1024; tt += 256) {
        const int n  = tt >> 4;
        const int wp = tt & 15;          // covers c = 4wp..4wp+3 in tile
        const float f0 = Ts[n * 65 + 4 * wp + 0];
        const float f1 = Ts[n * 65 + 4 * wp + 1];
        const float f2 = Ts[n * 65 + 4 * wp + 2];
        const float f3 = Ts[n * 65 + 4 * wp + 3];
        uint32_t h0, l0, h1, l1;
        splitbf(f0, f1, h0, l0);
        splitbf(f2, f3, h1, l1);
        const size_t di = ((size_t)b * NDIM + n0 + n) * (CDIM / 4) + (c0 >> 2) + wp;
        dh[di] = make_uint2(h0, h1);
        dl[di] = make_uint2(l0, l1);
    }
}

// ---------------------------------------------------------------------------
// Kernel 1: QKV projection, pure pre-split bf16 GEMM, cp.async double-buffered.
// Tile 128(o) x 128(n), k in 16 chunks of 32. 8 warps 2x4, warp 64x32.
// smem: 2 buffers x {Wh,Wl,Xh,Xl}[128 x GW] = 80 KB dynamic.
// Fragment layout identical to proven R11 scheme.
// ---------------------------------------------------------------------------
#define GW 20
#define GARR (128 * GW)                 // 2560 words
#define GEMM_SMEM_WORDS (8 * GARR)      // 20480 words = 81920 B

__global__ __launch_bounds__(256) void qkv_gemm_mma_kernel(
    const float* __restrict__ bq, const float* __restrict__ bk,
    const float* __restrict__ bv,
    const float* __restrict__ rel_h, const float* __restrict__ rel_w)
{
    extern __shared__ uint32_t gs[];
    const uint32_t gsb = (uint32_t)__cvta_generic_to_shared(gs);

    const int mat = blockIdx.z >> 4;   // 0=q, 1=k, 2=v
    const int b   = blockIdx.z & 15;
    const float* __restrict__ bias = (mat == 0) ? bq : (mat == 1) ? bk : bv;

    const int o0 = blockIdx.y * 128;
    const int n0 = blockIdx.x * 128;

    const int tid  = threadIdx.x;
    const int lane = tid & 31;
    const int warp = tid >> 5;
    const int g    = lane >> 2;
    const int t    = lane & 3;
    const int wm   = (warp >> 2) * 64;
    const int wn   = (warp & 3) * 32;

    // global uint4 pointers; each row = 256 words = 64 uint4
    const uint4* whb = (const uint4*)g_wh + ((size_t)mat * CDIM + o0) * 64;
    const uint4* wlb = (const uint4*)g_wl + ((size_t)mat * CDIM + o0) * 64;
    const uint4* xhb = (const uint4*)g_xh + ((size_t)b * NDIM + n0) * 64;
    const uint4* xlb = (const uint4*)g_xl + ((size_t)b * NDIM + n0) * 64;

    // issue chunks 0,1 (chunk = 16 words = 4 uint4 per row per array)
#pragma unroll
    for (int pc = 0; pc < 2; pc++) {
        const uint32_t base = gsb + pc * 4 * GARR * 4;
        for (int kk = tid; kk < 512; kk += 256) {
            const int r = kk >> 2, c = kk & 3;
            const uint32_t so = (uint32_t)(r * GW + c * 4) * 4;
            cpa16(base + so,               whb + (size_t)r * 64 + pc * 4 + c);
            cpa16(base + GARR * 4 + so,    wlb + (size_t)r * 64 + pc * 4 + c);
            cpa16(base + 2 * GARR * 4 + so, xhb + (size_t)r * 64 + pc * 4 + c);
            cpa16(base + 3 * GARR * 4 + so, xlb + (size_t)r * 64 + pc * 4 + c);
        }
        CP_COMMIT();
    }

    float acc[4][4][4];
#pragma unroll
    for (int mt = 0; mt < 4; mt++)
#pragma unroll
        for (int nt = 0; nt < 4; nt++)
#pragma unroll
            for (int c = 0; c < 4; c++) acc[mt][nt][c] = 0.f;

#pragma unroll 1
    for (int kc = 0; kc < 16; kc++) {
        if (kc < 15) { CP_WAIT1(); } else { CP_WAIT0(); }
        __syncthreads();

        const uint32_t* Wh = gs + (kc & 1) * 4 * GARR;
        const uint32_t* Wl = Wh + GARR;
        const uint32_t* Xh = Wh + 2 * GARR;
        const uint32_t* Xl = Wh + 3 * GARR;

#pragma unroll
        for (int ks = 0; ks < 2; ks++) {
            uint32_t Ah[4][4], Al[4][4];
#pragma unroll
            for (int mt = 0; mt < 4; mt++) {
                const int r0 = (wm + mt * 16 + g) * GW + ks * 8 + t;
                const int r1 = (wm + mt * 16 + 8 + g) * GW + ks * 8 + t;
                Ah[mt][0] = Wh[r0]; Ah[mt][1] = Wh[r1];
                Ah[mt][2] = Wh[r0 + 4]; Ah[mt][3] = Wh[r1 + 4];
                Al[mt][0] = Wl[r0]; Al[mt][1] = Wl[r1];
                Al[mt][2] = Wl[r0 + 4]; Al[mt][3] = Wl[r1 + 4];
            }
            uint32_t Bh[4][2], Bl[4][2];
#pragma unroll
            for (int nt = 0; nt < 4; nt++) {
                const int rr = (wn + nt * 8 + g) * GW + ks * 8 + t;
                Bh[nt][0] = Xh[rr]; Bh[nt][1] = Xh[rr + 4];
                Bl[nt][0] = Xl[rr]; Bl[nt][1] = Xl[rr + 4];
            }
#pragma unroll
            for (int mt = 0; mt < 4; mt++)
#pragma unroll
                for (int nt = 0; nt < 4; nt++) {
                    MMA_BF16(acc[mt][nt], Ah[mt], Bh[nt][0], Bh[nt][1]);
                    MMA_BF16(acc[mt][nt], Ah[mt], Bl[nt][0], Bl[nt][1]);
                    MMA_BF16(acc[mt][nt], Al[mt], Bh[nt][0], Bh[nt][1]);
                }
        }
        __syncthreads();

        if (kc + 2 < 16) {
            const uint32_t base = gsb + (kc & 1) * 4 * GARR * 4;
            const int kw4 = (kc + 2) * 4;
            for (int kk = tid; kk < 512; kk += 256) {
                const int r = kk >> 2, c = kk & 3;
                const uint32_t so = (uint32_t)(r * GW + c * 4) * 4;
                cpa16(base + so,               whb + (size_t)r * 64 + kw4 + c);
                cpa16(base + GARR * 4 + so,    wlb + (size_t)r * 64 + kw4 + c);
                cpa16(base + 2 * GARR * 4 + so, xhb + (size_t)r * 64 + kw4 + c);
                cpa16(base + 3 * GARR * 4 + so, xlb + (size_t)r * 64 + kw4 + c);
            }
            CP_COMMIT();
        }
    }

    // ---- epilogue (identical math to proven version) ----
    if (mat == 2) {
        uint32_t* __restrict__ vh = (uint32_t*)g_vh;
        uint32_t* __restrict__ vl = (uint32_t*)g_vl;
        const size_t vbase = (size_t)b * CDIM * (NDIM / 2);
#pragma unroll
        for (int mt = 0; mt < 4; mt++) {
            const int o_a = o0 + wm + mt * 16 + g;
            const int o_b = o_a + 8;
            const float bia = bias[o_a];
            const float bib = bias[o_b];
#pragma unroll
            for (int nt = 0; nt < 4; nt++) {
                const int n = n0 + wn + nt * 8 + 2 * t;
                uint32_t h, l;
                splitbf(acc[mt][nt][0] + bia, acc[mt][nt][1] + bia, h, l);
                size_t wa = vbase + (size_t)o_a * (NDIM / 2) + (n >> 1);
                vh[wa] = h; vl[wa] = l;
                splitbf(acc[mt][nt][2] + bib, acc[mt][nt][3] + bib, h, l);
                wa = vbase + (size_t)o_b * (NDIM / 2) + (n >> 1);
                vh[wa] = h; vl[wa] = l;
            }
        }
    } else {
        float* __restrict__ out = (mat == 0) ? g_q : g_k;
        const size_t obase = (size_t)b * CDIM * NDIM;
#pragma unroll
        for (int mt = 0; mt < 4; mt++) {
            const int o_a = o0 + wm + mt * 16 + g;
            const int o_b = o_a + 8;
            const float bia = bias[o_a];
            const float bib = bias[o_b];
            const int dda = o_a & 63;
            const int ddb = o_b & 63;
#pragma unroll
            for (int nt = 0; nt < 4; nt++) {
                const int n = n0 + wn + nt * 8 + 2 * t;
                float v0 = acc[mt][nt][0] + bia;
                float v1 = acc[mt][nt][1] + bia;
                float v2 = acc[mt][nt][2] + bib;
                float v3 = acc[mt][nt][3] + bib;
                if (mat == 0) {
                    v0 *= QSCALE; v1 *= QSCALE; v2 *= QSCALE; v3 *= QSCALE;
                } else {
                    v0 += rel_h[dda * 32 + (n >> 5)] + rel_w[dda * 32 + (n & 31)];
                    v1 += rel_h[dda * 32 + ((n + 1) >> 5)] + rel_w[dda * 32 + ((n + 1) & 31)];
                    v2 += rel_h[ddb * 32 + (n >> 5)] + rel_w[ddb * 32 + (n & 31)];
                    v3 += rel_h[ddb * 32 + ((n + 1) >> 5)] + rel_w[ddb * 32 + ((n + 1) & 31)];
                }
                *(float2*)&out[obase + (size_t)o_a * NDIM + n] = make_float2(v0, v1);
                *(float2*)&out[obase + (size_t)o_b * NDIM + n] = make_float2(v2, v3);
            }
        }
    }
}

// ---------------------------------------------------------------------------
// conv_qk: q,k fp32 [bh][d][n] -> split-bf16 [bh][i][d] (proven).
// ---------------------------------------------------------------------------
__global__ __launch_bounds__(256) void conv_qk_t_kernel()
{
    const int n0    = blockIdx.x * 64;
    const int bh    = blockIdx.y;
    const int which = blockIdx.z;

    const float* __restrict__ src =
        (which ? g_k : g_q) + (size_t)bh * DHEAD * NDIM;

    __shared__ float Ts[64 * 65];
    const int tid = threadIdx.x;

    for (int tt = tid; tt < 1024; tt += 256) {
        const int d  = tt >> 4;
        const int c4 = (tt & 15) * 4;
        const float4 v = *(const float4*)&src[(size_t)d * NDIM + n0 + c4];
        Ts[(c4 + 0) * 65 + d] = v.x;
        Ts[(c4 + 1) * 65 + d] = v.y;
        Ts[(c4 + 2) * 65 + d] = v.z;
        Ts[(c4 + 3) * 65 + d] = v.w;
    }
    __syncthreads();

    uint2* __restrict__ dh = (uint2*)(which ? g_kh : g_qh);
    uint2* __restrict__ dl = (uint2*)(which ? g_kl : g_ql);
    for (int tt = tid; tt < 1024; tt += 256) {
        const int n  = tt >> 4;
        const int wp = tt & 15;
        const float f0 = Ts[n * 65 + 4 * wp + 0];
        const float f1 = Ts[n * 65 + 4 * wp + 1];
        const float f2 = Ts[n * 65 + 4 * wp + 2];
        const float f3 = Ts[n * 65 + 4 * wp + 3];
        uint32_t h0, l0, h1, l1;
        splitbf(f0, f1, h0, l0);
        splitbf(f2, f3, h1, l1);
        const size_t di = ((size_t)bh * NDIM + n0 + n) * 16 + wp;
        dh[di] = make_uint2(h0, h1);
        dl[di] = make_uint2(l0, l1);
    }
}

// ---------------------------------------------------------------------------
// Kernel 2: flash attention (UNCHANGED — proven R12 cp.async version).
// ---------------------------------------------------------------------------
#define ROWW 36
#define ARR  (64 * ROWW)
#define ATTN_SMEM_WORDS (10 * ARR)

__global__ __launch_bounds__(128) void attn_mma_kernel(float* __restrict__ out)
{
    extern __shared__ uint32_t sw[];
    uint32_t* qsh = sw;
    uint32_t* qsl = sw + ARR;
    const uint32_t swb = (uint32_t)__cvta_generic_to_shared(sw);

    const int bh = blockIdx.y;
    const int i0 = blockIdx.x * 64;

    const int tid  = threadIdx.x;
    const int lane = tid & 31;
    const int warp = tid >> 5;
    const int g    = lane >> 2;
    const int t    = lane & 3;

    const uint4* khb = (const uint4*)(g_kh + (size_t)bh * NDIM * DHEAD);
    const uint4* klb = (const uint4*)(g_kl + (size_t)bh * NDIM * DHEAD);
    const uint4* vhb = (const uint4*)(g_vh + (size_t)bh * DHEAD * NDIM);
    const uint4* vlb = (const uint4*)(g_vl + (size_t)bh * DHEAD * NDIM);

#pragma unroll
    for (int pb = 0; pb < 2; pb++) {
        const int j0 = pb * 64;
        const uint32_t base = swb + (2 * ARR + pb * 4 * ARR) * 4;
        for (int kk = tid; kk < 512; kk += 128) {
            const int r = kk >> 3, c = kk & 7;
            const uint32_t so = (uint32_t)(r * ROWW + c * 4) * 4;
            cpa16(base + so,               khb + (size_t)(j0 + r) * 8 + c);
            cpa16(base + ARR * 4 + so,     klb + (size_t)(j0 + r) * 8 + c);
            cpa16(base + 2 * ARR * 4 + so, vhb + (size_t)r * 128 + (j0 >> 3) + c);
            cpa16(base + 3 * ARR * 4 + so, vlb + (size_t)r * 128 + (j0 >> 3) + c);
        }
        CP_COMMIT();
    }

    {
        const uint4* qh = (const uint4*)(g_qh + ((size_t)bh * NDIM + i0) * DHEAD);
        const uint4* ql = (const uint4*)(g_ql + ((size_t)bh * NDIM + i0) * DHEAD);
        for (int kk = tid; kk < 512; kk += 128) {
            const int r = kk >> 3, c = kk & 7;
            *(uint4*)&qsh[r * ROWW + c * 4] = qh[r * 8 + c];
            *(uint4*)&qsl[r * ROWW + c * 4] = ql[r * 8 + c];
        }
    }
    __syncthreads();

    uint32_t Ah[4][4], Al[4][4];
    {
        const int qr = warp * 16 + g;
#pragma unroll
        for (int ks = 0; ks < 4; ks++) {
            Ah[ks][0] = qsh[qr * ROWW + 8 * ks + t];
            Ah[ks][1] = qsh[(qr + 8) * ROWW + 8 * ks + t];
            Ah[ks][2] = qsh[qr * ROWW + 8 * ks + t + 4];
            Ah[ks][3] = qsh[(qr + 8) * ROWW + 8 * ks + t + 4];
            Al[ks][0] = qsl[qr * ROWW + 8 * ks + t];
            Al[ks][1] = qsl[(qr + 8) * ROWW + 8 * ks + t];
            Al[ks][2] = qsl[qr * ROWW + 8 * ks + t + 4];
            Al[ks][3] = qsl[(qr + 8) * ROWW + 8 * ks + t + 4];
        }
    }

    float m0 = -INFINITY, m1 = -INFINITY, l0 = 0.f, l1 = 0.f;
    float O[8][4];
#pragma unroll
    for (int nt = 0; nt < 8; nt++)
#pragma unroll
        for (int c = 0; c < 4; c++) O[nt][c] = 0.f;

#pragma unroll 1
    for (int jt = 0; jt < NDIM / 64; jt++) {
        if (jt < NDIM / 64 - 1) { CP_WAIT1(); } else { CP_WAIT0(); }
        __syncthreads();

        const uint32_t* ksh = sw + 2 * ARR + (jt & 1) * 4 * ARR;
        const uint32_t* ksl = ksh + ARR;
        const uint32_t* vsh = ksh + 2 * ARR;
        const uint32_t* vsl = ksh + 3 * ARR;

        float S[8][4];
#pragma unroll
        for (int nt = 0; nt < 8; nt++)
#pragma unroll
            for (int c = 0; c < 4; c++) S[nt][c] = 0.f;

#pragma unroll
        for (int nt = 0; nt < 8; nt++) {
            const int kr = (8 * nt + g) * ROWW;
#pragma unroll
            for (int ks = 0; ks < 4; ks++) {
                const uint32_t b0h = ksh[kr + 8 * ks + t];
                const uint32_t b1h = ksh[kr + 8 * ks + t + 4];
                const uint32_t b0l = ksl[kr + 8 * ks + t];
                const uint32_t b1l = ksl[kr + 8 * ks + t + 4];
                MMA_BF16(S[nt], Ah[ks], b0h, b1h);
                MMA_BF16(S[nt], Ah[ks], b0l, b1l);
                MMA_BF16(S[nt], Al[ks], b0h, b1h);
            }
        }

        float mx0 = S[0][0], mx1 = S[0][2];
#pragma unroll
        for (int nt = 0; nt < 8; nt++) {
            mx0 = fmaxf(mx0, fmaxf(S[nt][0], S[nt][1]));
            mx1 = fmaxf(mx1, fmaxf(S[nt][2], S[nt][3]));
        }
        mx0 = fmaxf(mx0, __shfl_xor_sync(0xffffffffu, mx0, 1));
        mx0 = fmaxf(mx0, __shfl_xor_sync(0xffffffffu, mx0, 2));
        mx1 = fmaxf(mx1, __shfl_xor_sync(0xffffffffu, mx1, 1));
        mx1 = fmaxf(mx1, __shfl_xor_sync(0xffffffffu, mx1, 2));

        const float mn0 = fmaxf(m0, mx0);
        const float mn1 = fmaxf(m1, mx1);
        const float al0 = __expf(m0 - mn0);
        const float al1 = __expf(m1 - mn1);
        m0 = mn0; m1 = mn1;

        float rs0 = 0.f, rs1 = 0.f;
#pragma unroll
        for (int nt = 0; nt < 8; nt++) {
            S[nt][0] = __expf(S[nt][0] - mn0); rs0 += S[nt][0];
            S[nt][1] = __expf(S[nt][1] - mn0); rs0 += S[nt][1];
            S[nt][2] = __expf(S[nt][2] - mn1); rs1 += S[nt][2];
            S[nt][3] = __expf(S[nt][3] - mn1); rs1 += S[nt][3];
        }
        rs0 += __shfl_xor_sync(0xffffffffu, rs0, 1);
        rs0 += __shfl_xor_sync(0xffffffffu, rs0, 2);
        rs1 += __shfl_xor_sync(0xffffffffu, rs1, 1);
        rs1 += __shfl_xor_sync(0xffffffffu, rs1, 2);
        l0 = l0 * al0 + rs0;
        l1 = l1 * al1 + rs1;

#pragma unroll
        for (int nt = 0; nt < 8; nt++) {
            O[nt][0] *= al0; O[nt][1] *= al0;
            O[nt][2] *= al1; O[nt][3] *= al1;
        }

#pragma unroll
        for (int kk = 0; kk < 4; kk++) {
            uint32_t Ph[4], Pl[4];
            splitbf(S[2 * kk][0],     S[2 * kk][1],     Ph[0], Pl[0]);
            splitbf(S[2 * kk][2],     S[2 * kk][3],     Ph[1], Pl[1]);
            splitbf(S[2 * kk + 1][0], S[2 * kk + 1][1], Ph[2], Pl[2]);
            splitbf(S[2 * kk + 1][2], S[2 * kk + 1][3], Ph[3], Pl[3]);
#pragma unroll
            for (int nt = 0; nt < 8; nt++) {
                const int vr = (8 * nt + g) * ROWW;
                const uint32_t b0h = vsh[vr + 8 * kk + t];
                const uint32_t b1h = vsh[vr + 8 * kk + t + 4];
                const uint32_t b0l = vsl[vr + 8 * kk + t];
                const uint32_t b1l = vsl[vr + 8 * kk + t + 4];
                MMA_BF16(O[nt], Ph, b0h, b1h);
                MMA_BF16(O[nt], Ph, b0l, b1l);
                MMA_BF16(O[nt], Pl, b0h, b1h);
            }
        }
        __syncthreads();

        if (jt + 2 < NDIM / 64) {
            const int j0 = (jt + 2) * 64;
            const uint32_t base = swb + (2 * ARR + (jt & 1) * 4 * ARR) * 4;
            for (int kk = tid; kk < 512; kk += 128) {
                const int r = kk >> 3, c = kk & 7;
                const uint32_t so = (uint32_t)(r * ROWW + c * 4) * 4;
                cpa16(base + so,               khb + (size_t)(j0 + r) * 8 + c);
                cpa16(base + ARR * 4 + so,     klb + (size_t)(j0 + r) * 8 + c);
                cpa16(base + 2 * ARR * 4 + so, vhb + (size_t)r * 128 + (j0 >> 3) + c);
                cpa16(base + 3 * ARR * 4 + so, vlb + (size_t)r * 128 + (j0 >> 3) + c);
            }
            CP_COMMIT();
        }
    }

    const float inv0 = 1.0f / l0;
    const float inv1 = 1.0f / l1;
    const int i = i0 + warp * 16 + g;
    float* __restrict__ op0 = out + ((size_t)bh * NDIM + i) * DHEAD;
    float* __restrict__ op1 = out + ((size_t)bh * NDIM + i + 8) * DHEAD;
#pragma unroll
    for (int nt = 0; nt < 8; nt++) {
        const int dd = 8 * nt + 2 * t;
        *(float2*)&op0[dd] = make_float2(O[nt][0] * inv0, O[nt][1] * inv0);
        *(float2*)&op1[dd] = make_float2(O[nt][2] * inv1, O[nt][3] * inv1);
    }
}

// ---------------------------------------------------------------------------
extern "C" void kernel_launch(void* const* d_in, const int* in_sizes, int n_in,
                              void* d_out, int out_size)
{
    const float* x     = (const float*)d_in[0];
    const float* Wq    = (const float*)d_in[1];
    const float* bq    = (const float*)d_in[2];
    const float* Wk    = (const float*)d_in[3];
    const float* bk    = (const float*)d_in[4];
    const float* Wv    = (const float*)d_in[5];
    const float* bv    = (const float*)d_in[6];
    const float* rel_h = (const float*)d_in[7];
    const float* rel_w = (const float*)d_in[8];
    float* out = (float*)d_out;

    cudaFuncSetAttribute(qkv_gemm_mma_kernel,
                         cudaFuncAttributeMaxDynamicSharedMemorySize,
                         GEMM_SMEM_WORDS * 4);
    cudaFuncSetAttribute(attn_mma_kernel,
                         cudaFuncAttributeMaxDynamicSharedMemorySize,
                         ATTN_SMEM_WORDS * 4);

    // 0) one-time operand splits
    conv_w_kernel<<<(3 * CDIM * CDIM / 4) / 256, 256>>>(Wq, Wk, Wv);
    dim3 gx(NDIM / 64, CDIM / 64, BDIM);
    conv_x_kernel<<<gx, 256>>>(x);

    // 1) QKV projections (pure split-bf16 GEMM; V emits split-bf16 directly)
    dim3 g1(NDIM / 128, CDIM / 128, 3 * BDIM);
    qkv_gemm_mma_kernel<<<g1, 256, GEMM_SMEM_WORDS * 4>>>(bq, bk, bv, rel_h, rel_w);

    // 2) split-bf16 conversion for q, k
    dim3 gc(NDIM / 64, NBH, 2);
    conv_qk_t_kernel<<<gc, 256>>>();

    // 3) tensor-core flash attention
    dim3 g2(NDIM / 64, NBH);
    attn_mma_kernel<<<g2, 128, ATTN_SMEM_WORDS * 4>>>(out);
}

// round 16
// speedup vs baseline: 2.8766x; 1.0582x over previous
#include <cstdint>
#include <stdint.h>
#include <cuda_runtime.h>
#include <cuda_bf16.h>
#include <math.h>

// Problem constants
#define BDIM 16
#define CDIM 512
#define NDIM 1024
#define NHEADS 8
#define DHEAD 64
#define QSCALE 0.125f
#define NBH (BDIM * NHEADS)

// pre-split GEMM operands
__device__ __nv_bfloat16 g_wh[3 * CDIM * CDIM];      // [mat][o][c-pair words]
__device__ __nv_bfloat16 g_wl[3 * CDIM * CDIM];
__device__ __nv_bfloat16 g_xh[BDIM * NDIM * CDIM];   // [b][n][c-pair words]
__device__ __nv_bfloat16 g_xl[BDIM * NDIM * CDIM];

// split-bf16 operands for attention (written directly by the GEMM epilogue)
__device__ __nv_bfloat16 g_qh[NBH * NDIM * DHEAD];   // [bh][i][d]
__device__ __nv_bfloat16 g_ql[NBH * NDIM * DHEAD];
__device__ __nv_bfloat16 g_kh[NBH * NDIM * DHEAD];   // [bh][j][d]
__device__ __nv_bfloat16 g_kl[NBH * NDIM * DHEAD];
__device__ __nv_bfloat16 g_vh[NBH * DHEAD * NDIM];   // [bh][d][j]
__device__ __nv_bfloat16 g_vl[NBH * DHEAD * NDIM];

// ---------------------------------------------------------------------------
__device__ __forceinline__ void splitbf(float a, float b,
                                        uint32_t& hi, uint32_t& lo)
{
    __nv_bfloat16 ah = __float2bfloat16_rn(a);
    __nv_bfloat16 bh = __float2bfloat16_rn(b);
    __nv_bfloat16 al = __float2bfloat16_rn(a - __bfloat162float(ah));
    __nv_bfloat16 bl = __float2bfloat16_rn(b - __bfloat162float(bh));
    __nv_bfloat162 h; h.x = ah; h.y = bh;
    __nv_bfloat162 l; l.x = al; l.y = bl;
    hi = *(uint32_t*)&h;
    lo = *(uint32_t*)&l;
}

// truncation split: 2 PRMT + 2 LOP + 2 FSUB, no slow cvt chains.
__device__ __forceinline__ void splitbf_trunc(float a, float b,
                                              uint32_t& hi, uint32_t& lo)
{
    const uint32_t ai = __float_as_uint(a);
    const uint32_t bi = __float_as_uint(b);
    hi = __byte_perm(ai, bi, 0x7632);
    const float ah = __uint_as_float(ai & 0xFFFF0000u);
    const float bh = __uint_as_float(bi & 0xFFFF0000u);
    lo = __byte_perm(__float_as_uint(a - ah), __float_as_uint(b - bh), 0x7632);
}

#define MMA_BF16(C, A, b0, b1)                                               \
    asm volatile(                                                            \
        "mma.sync.aligned.m16n8k16.row.col.f32.bf16.bf16.f32 "               \
        "{%0,%1,%2,%3},{%4,%5,%6,%7},{%8,%9},{%0,%1,%2,%3};\n"               \
        : "+f"((C)[0]), "+f"((C)[1]), "+f"((C)[2]), "+f"((C)[3])             \
        : "r"((A)[0]), "r"((A)[1]), "r"((A)[2]), "r"((A)[3]),                \
          "r"(b0), "r"(b1))

__device__ __forceinline__ void cpa16(uint32_t smem_addr, const void* gptr)
{
    asm volatile("cp.async.cg.shared.global [%0], [%1], 16;\n"
                 :: "r"(smem_addr), "l"(gptr));
}
#define CP_COMMIT() asm volatile("cp.async.commit_group;\n" ::: "memory")
#define CP_WAIT1()  asm volatile("cp.async.wait_group 1;\n" ::: "memory")
#define CP_WAIT0()  asm volatile("cp.async.wait_group 0;\n" ::: "memory")

// ---------------------------------------------------------------------------
// conv_w: W fp32 [o][c] -> split-bf16 c-pair words.
// ---------------------------------------------------------------------------
__global__ __launch_bounds__(256) void conv_w_kernel(
    const float* __restrict__ Wq, const float* __restrict__ Wk,
    const float* __restrict__ Wv)
{
    const size_t idx = (size_t)blockIdx.x * 256 + threadIdx.x;
    const int mat = (int)(idx / (CDIM * CDIM / 4));
    const size_t r = idx % (CDIM * CDIM / 4);
    const float* __restrict__ W = (mat == 0) ? Wq : (mat == 1) ? Wk : Wv;
    const float4 v = ((const float4*)W)[r];
    uint32_t h0, l0, h1, l1;
    splitbf(v.x, v.y, h0, l0);
    splitbf(v.z, v.w, h1, l1);
    ((uint2*)g_wh)[idx] = make_uint2(h0, h1);
    ((uint2*)g_wl)[idx] = make_uint2(l0, l1);
}

// ---------------------------------------------------------------------------
// conv_x: x fp32 [b][c][n] -> split-bf16 [b][n][c-pair words].
// ---------------------------------------------------------------------------
__global__ __launch_bounds__(256) void conv_x_kernel(const float* __restrict__ x)
{
    const int n0 = blockIdx.x * 64;
    const int c0 = blockIdx.y * 64;
    const int b  = blockIdx.z;

    const float* __restrict__ src = x + ((size_t)b * CDIM + c0) * NDIM;

    __shared__ float Ts[64 * 65];   // [n][c]
    const int tid = threadIdx.x;

    for (int tt = tid; tt < 1024; tt += 256) {
        const int c  = tt >> 4;
        const int n4 = (tt & 15) * 4;
        const float4 v = *(const float4*)&src[(size_t)c * NDIM + n0 + n4];
        Ts[(n4 + 0) * 65 + c] = v.x;
        Ts[(n4 + 1) * 65 + c] = v.y;
        Ts[(n4 + 2) * 65 + c] = v.z;
        Ts[(n4 + 3) * 65 + c] = v.w;
    }
    __syncthreads();

    uint2* __restrict__ dh = (uint2*)g_xh;
    uint2* __restrict__ dl = (uint2*)g_xl;
    for (int tt = tid; tt < 1024; tt += 256) {
        const int n  = tt >> 4;
        const int wp = tt & 15;
        const float f0 = Ts[n * 65 + 4 * wp + 0];
        const float f1 = Ts[n * 65 + 4 * wp + 1];
        const float f2 = Ts[n * 65 + 4 * wp + 2];
        const float f3 = Ts[n * 65 + 4 * wp + 3];
        uint32_t h0, l0, h1, l1;
        splitbf(f0, f1, h0, l0);
        splitbf(f2, f3, h1, l1);
        const size_t di = ((size_t)b * NDIM + n0 + n) * (CDIM / 4) + (c0 >> 2) + wp;
        dh[di] = make_uint2(h0, h1);
        dl[di] = make_uint2(l0, l1);
    }
}

// ---------------------------------------------------------------------------
// Kernel 1: QKV projection, pre-split bf16 GEMM, cp.async double-buffered.
// NEW: q/k epilogue stages the fp32 tile in (now-dead) smem, transposes, and
// emits split-bf16 [bh][i][d] directly — conv_qk and fp32 scratch eliminated.
// ---------------------------------------------------------------------------
#define GW 20
#define GARR (128 * GW)                 // 2560 words
#define GEMM_SMEM_WORDS (8 * GARR)      // 20480 words = 81920 B (>= 128*132*4)

__global__ __launch_bounds__(256) void qkv_gemm_mma_kernel(
    const float* __restrict__ bq, const float* __restrict__ bk,
    const float* __restrict__ bv,
    const float* __restrict__ rel_h, const float* __restrict__ rel_w)
{
    extern __shared__ uint32_t gs[];
    const uint32_t gsb = (uint32_t)__cvta_generic_to_shared(gs);

    const int mat = blockIdx.z >> 4;   // 0=q, 1=k, 2=v
    const int b   = blockIdx.z & 15;
    const float* __restrict__ bias = (mat == 0) ? bq : (mat == 1) ? bk : bv;

    const int o0 = blockIdx.y * 128;
    const int n0 = blockIdx.x * 128;

    const int tid  = threadIdx.x;
    const int lane = tid & 31;
    const int warp = tid >> 5;
    const int g    = lane >> 2;
    const int t    = lane & 3;
    const int wm   = (warp >> 2) * 64;
    const int wn   = (warp & 3) * 32;

    const uint4* whb = (const uint4*)g_wh + ((size_t)mat * CDIM + o0) * 64;
    const uint4* wlb = (const uint4*)g_wl + ((size_t)mat * CDIM + o0) * 64;
    const uint4* xhb = (const uint4*)g_xh + ((size_t)b * NDIM + n0) * 64;
    const uint4* xlb = (const uint4*)g_xl + ((size_t)b * NDIM + n0) * 64;

#pragma unroll
    for (int pc = 0; pc < 2; pc++) {
        const uint32_t base = gsb + pc * 4 * GARR * 4;
        for (int kk = tid; kk < 512; kk += 256) {
            const int r = kk >> 2, c = kk & 3;
            const uint32_t so = (uint32_t)(r * GW + c * 4) * 4;
            cpa16(base + so,                whb + (size_t)r * 64 + pc * 4 + c);
            cpa16(base + GARR * 4 + so,     wlb + (size_t)r * 64 + pc * 4 + c);
            cpa16(base + 2 * GARR * 4 + so, xhb + (size_t)r * 64 + pc * 4 + c);
            cpa16(base + 3 * GARR * 4 + so, xlb + (size_t)r * 64 + pc * 4 + c);
        }
        CP_COMMIT();
    }

    float acc[4][4][4];
#pragma unroll
    for (int mt = 0; mt < 4; mt++)
#pragma unroll
        for (int nt = 0; nt < 4; nt++)
#pragma unroll
            for (int c = 0; c < 4; c++) acc[mt][nt][c] = 0.f;

#pragma unroll 1
    for (int kc = 0; kc < 16; kc++) {
        if (kc < 15) { CP_WAIT1(); } else { CP_WAIT0(); }
        __syncthreads();

        const uint32_t* Wh = gs + (kc & 1) * 4 * GARR;
        const uint32_t* Wl = Wh + GARR;
        const uint32_t* Xh = Wh + 2 * GARR;
        const uint32_t* Xl = Wh + 3 * GARR;

#pragma unroll
        for (int ks = 0; ks < 2; ks++) {
            uint32_t Ah[4][4], Al[4][4];
#pragma unroll
            for (int mt = 0; mt < 4; mt++) {
                const int r0 = (wm + mt * 16 + g) * GW + ks * 8 + t;
                const int r1 = (wm + mt * 16 + 8 + g) * GW + ks * 8 + t;
                Ah[mt][0] = Wh[r0]; Ah[mt][1] = Wh[r1];
                Ah[mt][2] = Wh[r0 + 4]; Ah[mt][3] = Wh[r1 + 4];
                Al[mt][0] = Wl[r0]; Al[mt][1] = Wl[r1];
                Al[mt][2] = Wl[r0 + 4]; Al[mt][3] = Wl[r1 + 4];
            }
            uint32_t Bh[4][2], Bl[4][2];
#pragma unroll
            for (int nt = 0; nt < 4; nt++) {
                const int rr = (wn + nt * 8 + g) * GW + ks * 8 + t;
                Bh[nt][0] = Xh[rr]; Bh[nt][1] = Xh[rr + 4];
                Bl[nt][0] = Xl[rr]; Bl[nt][1] = Xl[rr + 4];
            }
#pragma unroll
            for (int mt = 0; mt < 4; mt++)
#pragma unroll
                for (int nt = 0; nt < 4; nt++) {
                    MMA_BF16(acc[mt][nt], Ah[mt], Bh[nt][0], Bh[nt][1]);
                    MMA_BF16(acc[mt][nt], Ah[mt], Bl[nt][0], Bl[nt][1]);
                    MMA_BF16(acc[mt][nt], Al[mt], Bh[nt][0], Bh[nt][1]);
                }
        }
        __syncthreads();

        if (kc + 2 < 16) {
            const uint32_t base = gsb + (kc & 1) * 4 * GARR * 4;
            const int kw4 = (kc + 2) * 4;
            for (int kk = tid; kk < 512; kk += 256) {
                const int r = kk >> 2, c = kk & 3;
                const uint32_t so = (uint32_t)(r * GW + c * 4) * 4;
                cpa16(base + so,                whb + (size_t)r * 64 + kw4 + c);
                cpa16(base + GARR * 4 + so,     wlb + (size_t)r * 64 + kw4 + c);
                cpa16(base + 2 * GARR * 4 + so, xhb + (size_t)r * 64 + kw4 + c);
                cpa16(base + 3 * GARR * 4 + so, xlb + (size_t)r * 64 + kw4 + c);
            }
            CP_COMMIT();
        }
    }
    // (last loop iteration ended with __syncthreads: smem is free for staging)

    if (mat == 2) {
        // V: write split-bf16 [bh][d][j] directly (word = n-pair), as proven.
        uint32_t* __restrict__ vh = (uint32_t*)g_vh;
        uint32_t* __restrict__ vl = (uint32_t*)g_vl;
        const size_t vbase = (size_t)b * CDIM * (NDIM / 2);
#pragma unroll
        for (int mt = 0; mt < 4; mt++) {
            const int o_a = o0 + wm + mt * 16 + g;
            const int o_b = o_a + 8;
            const float bia = bias[o_a];
            const float bib = bias[o_b];
#pragma unroll
            for (int nt = 0; nt < 4; nt++) {
                const int n = n0 + wn + nt * 8 + 2 * t;
                uint32_t h, l;
                splitbf(acc[mt][nt][0] + bia, acc[mt][nt][1] + bia, h, l);
                size_t wa = vbase + (size_t)o_a * (NDIM / 2) + (n >> 1);
                vh[wa] = h; vl[wa] = l;
                splitbf(acc[mt][nt][2] + bib, acc[mt][nt][3] + bib, h, l);
                wa = vbase + (size_t)o_b * (NDIM / 2) + (n >> 1);
                vh[wa] = h; vl[wa] = l;
            }
        }
    } else {
        // q/k: stage fp32 tile [n_local][o_local] (stride 132) with epilogue
        // math applied, then transpose+split straight to [bh][i][d].
        float* __restrict__ Ep = (float*)gs;
#pragma unroll
        for (int mt = 0; mt < 4; mt++) {
            const int ol_a = wm + mt * 16 + g;
            const int ol_b = ol_a + 8;
            const int o_a = o0 + ol_a;
            const int o_b = o0 + ol_b;
            const float bia = bias[o_a];
            const float bib = bias[o_b];
            const int dda = o_a & 63;
            const int ddb = o_b & 63;
#pragma unroll
            for (int nt = 0; nt < 4; nt++) {
                const int nl = wn + nt * 8 + 2 * t;
                const int n  = n0 + nl;
                float v0 = acc[mt][nt][0] + bia;
                float v1 = acc[mt][nt][1] + bia;
                float v2 = acc[mt][nt][2] + bib;
                float v3 = acc[mt][nt][3] + bib;
                if (mat == 0) {
                    v0 *= QSCALE; v1 *= QSCALE; v2 *= QSCALE; v3 *= QSCALE;
                } else {
                    v0 += rel_h[dda * 32 + (n >> 5)] + rel_w[dda * 32 + (n & 31)];
                    v1 += rel_h[dda * 32 + ((n + 1) >> 5)] + rel_w[dda * 32 + ((n + 1) & 31)];
                    v2 += rel_h[ddb * 32 + (n >> 5)] + rel_w[ddb * 32 + (n & 31)];
                    v3 += rel_h[ddb * 32 + ((n + 1) >> 5)] + rel_w[ddb * 32 + ((n + 1) & 31)];
                }
                Ep[(nl + 0) * 132 + ol_a] = v0;
                Ep[(nl + 1) * 132 + ol_a] = v1;
                Ep[(nl + 0) * 132 + ol_b] = v2;
                Ep[(nl + 1) * 132 + ol_b] = v3;
            }
        }
        __syncthreads();

        uint2* __restrict__ dh = (uint2*)(mat ? g_kh : g_qh);
        uint2* __restrict__ dl = (uint2*)(mat ? g_kl : g_ql);
        const int h0 = o0 >> 6;   // first of the 2 heads this o-block covers
        for (int tt = tid; tt < 4096; tt += 256) {
            const int il   = tt >> 5;          // 0..127 (i = n0 + il)
            const int rem  = tt & 31;
            const int head = rem >> 4;         // 0..1
            const int wp   = rem & 15;         // d-word-pair: d = 4wp..4wp+3
            const float4 f = *(const float4*)&Ep[il * 132 + head * 64 + 4 * wp];
            uint32_t hh0, ll0, hh1, ll1;
            splitbf(f.x, f.y, hh0, ll0);
            splitbf(f.z, f.w, hh1, ll1);
            const size_t di =
                ((size_t)(b * NHEADS + h0 + head) * NDIM + n0 + il) * 16 + wp;
            dh[di] = make_uint2(hh0, hh1);
            dl[di] = make_uint2(ll0, ll1);
        }
    }
}

// ---------------------------------------------------------------------------
// Kernel 2: flash attention (proven R12 cp.async version; P-split -> trunc).
// ---------------------------------------------------------------------------
#define ROWW 36
#define ARR  (64 * ROWW)
#define ATTN_SMEM_WORDS (10 * ARR)

__global__ __launch_bounds__(128) void attn_mma_kernel(float* __restrict__ out)
{
    extern __shared__ uint32_t sw[];
    uint32_t* qsh = sw;
    uint32_t* qsl = sw + ARR;
    const uint32_t swb = (uint32_t)__cvta_generic_to_shared(sw);

    const int bh = blockIdx.y;
    const int i0 = blockIdx.x * 64;

    const int tid  = threadIdx.x;
    const int lane = tid & 31;
    const int warp = tid >> 5;
    const int g    = lane >> 2;
    const int t    = lane & 3;

    const uint4* khb = (const uint4*)(g_kh + (size_t)bh * NDIM * DHEAD);
    const uint4* klb = (const uint4*)(g_kl + (size_t)bh * NDIM * DHEAD);
    const uint4* vhb = (const uint4*)(g_vh + (size_t)bh * DHEAD * NDIM);
    const uint4* vlb = (const uint4*)(g_vl + (size_t)bh * DHEAD * NDIM);

#pragma unroll
    for (int pb = 0; pb < 2; pb++) {
        const int j0 = pb * 64;
        const uint32_t base = swb + (2 * ARR + pb * 4 * ARR) * 4;
        for (int kk = tid; kk < 512; kk += 128) {
            const int r = kk >> 3, c = kk & 7;
            const uint32_t so = (uint32_t)(r * ROWW + c * 4) * 4;
            cpa16(base + so,               khb + (size_t)(j0 + r) * 8 + c);
            cpa16(base + ARR * 4 + so,     klb + (size_t)(j0 + r) * 8 + c);
            cpa16(base + 2 * ARR * 4 + so, vhb + (size_t)r * 128 + (j0 >> 3) + c);
            cpa16(base + 3 * ARR * 4 + so, vlb + (size_t)r * 128 + (j0 >> 3) + c);
        }
        CP_COMMIT();
    }

    {
        const uint4* qh = (const uint4*)(g_qh + ((size_t)bh * NDIM + i0) * DHEAD);
        const uint4* ql = (const uint4*)(g_ql + ((size_t)bh * NDIM + i0) * DHEAD);
        for (int kk = tid; kk < 512; kk += 128) {
            const int r = kk >> 3, c = kk & 7;
            *(uint4*)&qsh[r * ROWW + c * 4] = qh[r * 8 + c];
            *(uint4*)&qsl[r * ROWW + c * 4] = ql[r * 8 + c];
        }
    }
    __syncthreads();

    uint32_t Ah[4][4], Al[4][4];
    {
        const int qr = warp * 16 + g;
#pragma unroll
        for (int ks = 0; ks < 4; ks++) {
            Ah[ks][0] = qsh[qr * ROWW + 8 * ks + t];
            Ah[ks][1] = qsh[(qr + 8) * ROWW + 8 * ks + t];
            Ah[ks][2] = qsh[qr * ROWW + 8 * ks + t + 4];
            Ah[ks][3] = qsh[(qr + 8) * ROWW + 8 * ks + t + 4];
            Al[ks][0] = qsl[qr * ROWW + 8 * ks + t];
            Al[ks][1] = qsl[(qr + 8) * ROWW + 8 * ks + t];
            Al[ks][2] = qsl[qr * ROWW + 8 * ks + t + 4];
            Al[ks][3] = qsl[(qr + 8) * ROWW + 8 * ks + t + 4];
        }
    }

    float m0 = -INFINITY, m1 = -INFINITY, l0 = 0.f, l1 = 0.f;
    float O[8][4];
#pragma unroll
    for (int nt = 0; nt < 8; nt++)
#pragma unroll
        for (int c = 0; c < 4; c++) O[nt][c] = 0.f;

#pragma unroll 1
    for (int jt = 0; jt < NDIM / 64; jt++) {
        if (jt < NDIM / 64 - 1) { CP_WAIT1(); } else { CP_WAIT0(); }
        __syncthreads();

        const uint32_t* ksh = sw + 2 * ARR + (jt & 1) * 4 * ARR;
        const uint32_t* ksl = ksh + ARR;
        const uint32_t* vsh = ksh + 2 * ARR;
        const uint32_t* vsl = ksh + 3 * ARR;

        float S[8][4];
#pragma unroll
        for (int nt = 0; nt < 8; nt++)
#pragma unroll
            for (int c = 0; c < 4; c++) S[nt][c] = 0.f;

#pragma unroll
        for (int nt = 0; nt < 8; nt++) {
            const int kr = (8 * nt + g) * ROWW;
#pragma unroll
            for (int ks = 0; ks < 4; ks++) {
                const uint32_t b0h = ksh[kr + 8 * ks + t];
                const uint32_t b1h = ksh[kr + 8 * ks + t + 4];
                const uint32_t b0l = ksl[kr + 8 * ks + t];
                const uint32_t b1l = ksl[kr + 8 * ks + t + 4];
                MMA_BF16(S[nt], Ah[ks], b0h, b1h);
                MMA_BF16(S[nt], Ah[ks], b0l, b1l);
                MMA_BF16(S[nt], Al[ks], b0h, b1h);
            }
        }

        float mx0 = S[0][0], mx1 = S[0][2];
#pragma unroll
        for (int nt = 0; nt < 8; nt++) {
            mx0 = fmaxf(mx0, fmaxf(S[nt][0], S[nt][1]));
            mx1 = fmaxf(mx1, fmaxf(S[nt][2], S[nt][3]));
        }
        mx0 = fmaxf(mx0, __shfl_xor_sync(0xffffffffu, mx0, 1));
        mx0 = fmaxf(mx0, __shfl_xor_sync(0xffffffffu, mx0, 2));
        mx1 = fmaxf(mx1, __shfl_xor_sync(0xffffffffu, mx1, 1));
        mx1 = fmaxf(mx1, __shfl_xor_sync(0xffffffffu, mx1, 2));

        const float mn0 = fmaxf(m0, mx0);
        const float mn1 = fmaxf(m1, mx1);
        const float al0 = __expf(m0 - mn0);
        const float al1 = __expf(m1 - mn1);
        m0 = mn0; m1 = mn1;

        float rs0 = 0.f, rs1 = 0.f;
#pragma unroll
        for (int nt = 0; nt < 8; nt++) {
            S[nt][0] = __expf(S[nt][0] - mn0); rs0 += S[nt][0];
            S[nt][1] = __expf(S[nt][1] - mn0); rs0 += S[nt][1];
            S[nt][2] = __expf(S[nt][2] - mn1); rs1 += S[nt][2];
            S[nt][3] = __expf(S[nt][3] - mn1); rs1 += S[nt][3];
        }
        rs0 += __shfl_xor_sync(0xffffffffu, rs0, 1);
        rs0 += __shfl_xor_sync(0xffffffffu, rs0, 2);
        rs1 += __shfl_xor_sync(0xffffffffu, rs1, 1);
        rs1 += __shfl_xor_sync(0xffffffffu, rs1, 2);
        l0 = l0 * al0 + rs0;
        l1 = l1 * al1 + rs1;

#pragma unroll
        for (int nt = 0; nt < 8; nt++) {
            O[nt][0] *= al0; O[nt][1] *= al0;
            O[nt][2] *= al1; O[nt][3] *= al1;
        }

#pragma unroll
        for (int kk = 0; kk < 4; kk++) {
            uint32_t Ph[4], Pl[4];
            splitbf_trunc(S[2 * kk][0],     S[2 * kk][1],     Ph[0], Pl[0]);
            splitbf_trunc(S[2 * kk][2],     S[2 * kk][3],     Ph[1], Pl[1]);
            splitbf_trunc(S[2 * kk + 1][0], S[2 * kk + 1][1], Ph[2], Pl[2]);
            splitbf_trunc(S[2 * kk + 1][2], S[2 * kk + 1][3], Ph[3], Pl[3]);
#pragma unroll
            for (int nt = 0; nt < 8; nt++) {
                const int vr = (8 * nt + g) * ROWW;
                const uint32_t b0h = vsh[vr + 8 * kk + t];
                const uint32_t b1h = vsh[vr + 8 * kk + t + 4];
                const uint32_t b0l = vsl[vr + 8 * kk + t];
                const uint32_t b1l = vsl[vr + 8 * kk + t + 4];
                MMA_BF16(O[nt], Ph, b0h, b1h);
                MMA_BF16(O[nt], Ph, b0l, b1l);
                MMA_BF16(O[nt], Pl, b0h, b1h);
            }
        }
        __syncthreads();

        if (jt + 2 < NDIM / 64) {
            const int j0 = (jt + 2) * 64;
            const uint32_t base = swb + (2 * ARR + (jt & 1) * 4 * ARR) * 4;
            for (int kk = tid; kk < 512; kk += 128) {
                const int r = kk >> 3, c = kk & 7;
                const uint32_t so = (uint32_t)(r * ROWW + c * 4) * 4;
                cpa16(base + so,               khb + (size_t)(j0 + r) * 8 + c);
                cpa16(base + ARR * 4 + so,     klb + (size_t)(j0 + r) * 8 + c);
                cpa16(base + 2 * ARR * 4 + so, vhb + (size_t)r * 128 + (j0 >> 3) + c);
                cpa16(base + 3 * ARR * 4 + so, vlb + (size_t)r * 128 + (j0 >> 3) + c);
            }
            CP_COMMIT();
        }
    }

    const float inv0 = 1.0f / l0;
    const float inv1 = 1.0f / l1;
    const int i = i0 + warp * 16 + g;
    float* __restrict__ op0 = out + ((size_t)bh * NDIM + i) * DHEAD;
    float* __restrict__ op1 = out + ((size_t)bh * NDIM + i + 8) * DHEAD;
#pragma unroll
    for (int nt = 0; nt < 8; nt++) {
        const int dd = 8 * nt + 2 * t;
        *(float2*)&op0[dd] = make_float2(O[nt][0] * inv0, O[nt][1] * inv0);
        *(float2*)&op1[dd] = make_float2(O[nt][2] * inv1, O[nt][3] * inv1);
    }
}

// ---------------------------------------------------------------------------
extern "C" void kernel_launch(void* const* d_in, const int* in_sizes, int n_in,
                              void* d_out, int out_size)
{
    const float* x     = (const float*)d_in[0];
    const float* Wq    = (const float*)d_in[1];
    const float* bq    = (const float*)d_in[2];
    const float* Wk    = (const float*)d_in[3];
    const float* bk    = (const float*)d_in[4];
    const float* Wv    = (const float*)d_in[5];
    const float* bv    = (const float*)d_in[6];
    const float* rel_h = (const float*)d_in[7];
    const float* rel_w = (const float*)d_in[8];
    float* out = (float*)d_out;

    cudaFuncSetAttribute(qkv_gemm_mma_kernel,
                         cudaFuncAttributeMaxDynamicSharedMemorySize,
                         GEMM_SMEM_WORDS * 4);
    cudaFuncSetAttribute(attn_mma_kernel,
                         cudaFuncAttributeMaxDynamicSharedMemorySize,
                         ATTN_SMEM_WORDS * 4);

    // 0) one-time operand splits
    conv_w_kernel<<<(3 * CDIM * CDIM / 4) / 256, 256>>>(Wq, Wk, Wv);
    dim3 gx(NDIM / 64, CDIM / 64, BDIM);
    conv_x_kernel<<<gx, 256>>>(x);

    // 1) QKV projections (q/k/v all emit split-bf16 directly)
    dim3 g1(NDIM / 128, CDIM / 128, 3 * BDIM);
    qkv_gemm_mma_kernel<<<g1, 256, GEMM_SMEM_WORDS * 4>>>(bq, bk, bv, rel_h, rel_w);

    // 2) tensor-core flash attention
    dim3 g2(NDIM / 64, NBH);
    attn_mma_kernel<<<g2, 128, ATTN_SMEM_WORDS * 4>>>(out);
}

// round 17
// speedup vs baseline: 2.9953x; 1.0413x over previous
#include <cstdint>
#include <stdint.h>
#include <cuda_runtime.h>
#include <cuda_bf16.h>
#include <math.h>

// Problem constants
#define BDIM 16
#define CDIM 512
#define NDIM 1024
#define NHEADS 8
#define DHEAD 64
#define QSCALE 0.125f
#define NBH (BDIM * NHEADS)

// pre-split GEMM operands
__device__ __nv_bfloat16 g_wh[3 * CDIM * CDIM];      // [mat][o][c-pair words]
__device__ __nv_bfloat16 g_wl[3 * CDIM * CDIM];
__device__ __nv_bfloat16 g_xh[BDIM * NDIM * CDIM];   // [b][n][c-pair words]
__device__ __nv_bfloat16 g_xl[BDIM * NDIM * CDIM];

// split-bf16 operands for attention (written directly by the GEMM epilogue)
__device__ __nv_bfloat16 g_qh[NBH * NDIM * DHEAD];   // [bh][i][d]
__device__ __nv_bfloat16 g_ql[NBH * NDIM * DHEAD];
__device__ __nv_bfloat16 g_kh[NBH * NDIM * DHEAD];   // [bh][j][d]
__device__ __nv_bfloat16 g_kl[NBH * NDIM * DHEAD];
__device__ __nv_bfloat16 g_vh[NBH * DHEAD * NDIM];   // [bh][d][j]
__device__ __nv_bfloat16 g_vl[NBH * DHEAD * NDIM];

// ---------------------------------------------------------------------------
__device__ __forceinline__ void splitbf(float a, float b,
                                        uint32_t& hi, uint32_t& lo)
{
    __nv_bfloat16 ah = __float2bfloat16_rn(a);
    __nv_bfloat16 bh = __float2bfloat16_rn(b);
    __nv_bfloat16 al = __float2bfloat16_rn(a - __bfloat162float(ah));
    __nv_bfloat16 bl = __float2bfloat16_rn(b - __bfloat162float(bh));
    __nv_bfloat162 h; h.x = ah; h.y = bh;
    __nv_bfloat162 l; l.x = al; l.y = bl;
    hi = *(uint32_t*)&h;
    lo = *(uint32_t*)&l;
}

// truncation split: 2 PRMT + 2 LOP + 2 FSUB, no slow cvt chains.
__device__ __forceinline__ void splitbf_trunc(float a, float b,
                                              uint32_t& hi, uint32_t& lo)
{
    const uint32_t ai = __float_as_uint(a);
    const uint32_t bi = __float_as_uint(b);
    hi = __byte_perm(ai, bi, 0x7632);
    const float ah = __uint_as_float(ai & 0xFFFF0000u);
    const float bh = __uint_as_float(bi & 0xFFFF0000u);
    lo = __byte_perm(__float_as_uint(a - ah), __float_as_uint(b - bh), 0x7632);
}

#define MMA_BF16(C, A, b0, b1)                                               \
    asm volatile(                                                            \
        "mma.sync.aligned.m16n8k16.row.col.f32.bf16.bf16.f32 "               \
        "{%0,%1,%2,%3},{%4,%5,%6,%7},{%8,%9},{%0,%1,%2,%3};\n"               \
        : "+f"((C)[0]), "+f"((C)[1]), "+f"((C)[2]), "+f"((C)[3])             \
        : "r"((A)[0]), "r"((A)[1]), "r"((A)[2]), "r"((A)[3]),                \
          "r"(b0), "r"(b1))

__device__ __forceinline__ void cpa16(uint32_t smem_addr, const void* gptr)
{
    asm volatile("cp.async.cg.shared.global [%0], [%1], 16;\n"
                 :: "r"(smem_addr), "l"(gptr));
}
#define CP_COMMIT() asm volatile("cp.async.commit_group;\n" ::: "memory")
#define CP_WAIT1()  asm volatile("cp.async.wait_group 1;\n" ::: "memory")
#define CP_WAIT0()  asm volatile("cp.async.wait_group 0;\n" ::: "memory")

// ---------------------------------------------------------------------------
// conv_w: W fp32 [o][c] -> split-bf16 c-pair words.
// ---------------------------------------------------------------------------
__global__ __launch_bounds__(256) void conv_w_kernel(
    const float* __restrict__ Wq, const float* __restrict__ Wk,
    const float* __restrict__ Wv)
{
    const size_t idx = (size_t)blockIdx.x * 256 + threadIdx.x;
    const int mat = (int)(idx / (CDIM * CDIM / 4));
    const size_t r = idx % (CDIM * CDIM / 4);
    const float* __restrict__ W = (mat == 0) ? Wq : (mat == 1) ? Wk : Wv;
    const float4 v = ((const float4*)W)[r];
    uint32_t h0, l0, h1, l1;
    splitbf(v.x, v.y, h0, l0);
    splitbf(v.z, v.w, h1, l1);
    ((uint2*)g_wh)[idx] = make_uint2(h0, h1);
    ((uint2*)g_wl)[idx] = make_uint2(l0, l1);
}

// ---------------------------------------------------------------------------
// conv_x: x fp32 [b][c][n] -> split-bf16 [b][n][c-pair words].
// ---------------------------------------------------------------------------
__global__ __launch_bounds__(256) void conv_x_kernel(const float* __restrict__ x)
{
    const int n0 = blockIdx.x * 64;
    const int c0 = blockIdx.y * 64;
    const int b  = blockIdx.z;

    const float* __restrict__ src = x + ((size_t)b * CDIM + c0) * NDIM;

    __shared__ float Ts[64 * 65];   // [n][c]
    const int tid = threadIdx.x;

    for (int tt = tid; tt < 1024; tt += 256) {
        const int c  = tt >> 4;
        const int n4 = (tt & 15) * 4;
        const float4 v = *(const float4*)&src[(size_t)c * NDIM + n0 + n4];
        Ts[(n4 + 0) * 65 + c] = v.x;
        Ts[(n4 + 1) * 65 + c] = v.y;
        Ts[(n4 + 2) * 65 + c] = v.z;
        Ts[(n4 + 3) * 65 + c] = v.w;
    }
    __syncthreads();

    uint2* __restrict__ dh = (uint2*)g_xh;
    uint2* __restrict__ dl = (uint2*)g_xl;
    for (int tt = tid; tt < 1024; tt += 256) {
        const int n  = tt >> 4;
        const int wp = tt & 15;
        const float f0 = Ts[n * 65 + 4 * wp + 0];
        const float f1 = Ts[n * 65 + 4 * wp + 1];
        const float f2 = Ts[n * 65 + 4 * wp + 2];
        const float f3 = Ts[n * 65 + 4 * wp + 3];
        uint32_t h0, l0, h1, l1;
        splitbf(f0, f1, h0, l0);
        splitbf(f2, f3, h1, l1);
        const size_t di = ((size_t)b * NDIM + n0 + n) * (CDIM / 4) + (c0 >> 2) + wp;
        dh[di] = make_uint2(h0, h1);
        dl[di] = make_uint2(l0, l1);
    }
}

// ---------------------------------------------------------------------------
// Kernel 1: QKV projection (UNCHANGED from proven R15 version).
// ---------------------------------------------------------------------------
#define GW 20
#define GARR (128 * GW)                 // 2560 words
#define GEMM_SMEM_WORDS (8 * GARR)      // 20480 words = 81920 B

__global__ __launch_bounds__(256) void qkv_gemm_mma_kernel(
    const float* __restrict__ bq, const float* __restrict__ bk,
    const float* __restrict__ bv,
    const float* __restrict__ rel_h, const float* __restrict__ rel_w)
{
    extern __shared__ uint32_t gs[];
    const uint32_t gsb = (uint32_t)__cvta_generic_to_shared(gs);

    const int mat = blockIdx.z >> 4;   // 0=q, 1=k, 2=v
    const int b   = blockIdx.z & 15;
    const float* __restrict__ bias = (mat == 0) ? bq : (mat == 1) ? bk : bv;

    const int o0 = blockIdx.y * 128;
    const int n0 = blockIdx.x * 128;

    const int tid  = threadIdx.x;
    const int lane = tid & 31;
    const int warp = tid >> 5;
    const int g    = lane >> 2;
    const int t    = lane & 3;
    const int wm   = (warp >> 2) * 64;
    const int wn   = (warp & 3) * 32;

    const uint4* whb = (const uint4*)g_wh + ((size_t)mat * CDIM + o0) * 64;
    const uint4* wlb = (const uint4*)g_wl + ((size_t)mat * CDIM + o0) * 64;
    const uint4* xhb = (const uint4*)g_xh + ((size_t)b * NDIM + n0) * 64;
    const uint4* xlb = (const uint4*)g_xl + ((size_t)b * NDIM + n0) * 64;

#pragma unroll
    for (int pc = 0; pc < 2; pc++) {
        const uint32_t base = gsb + pc * 4 * GARR * 4;
        for (int kk = tid; kk < 512; kk += 256) {
            const int r = kk >> 2, c = kk & 3;
            const uint32_t so = (uint32_t)(r * GW + c * 4) * 4;
            cpa16(base + so,                whb + (size_t)r * 64 + pc * 4 + c);
            cpa16(base + GARR * 4 + so,     wlb + (size_t)r * 64 + pc * 4 + c);
            cpa16(base + 2 * GARR * 4 + so, xhb + (size_t)r * 64 + pc * 4 + c);
            cpa16(base + 3 * GARR * 4 + so, xlb + (size_t)r * 64 + pc * 4 + c);
        }
        CP_COMMIT();
    }

    float acc[4][4][4];
#pragma unroll
    for (int mt = 0; mt < 4; mt++)
#pragma unroll
        for (int nt = 0; nt < 4; nt++)
#pragma unroll
            for (int c = 0; c < 4; c++) acc[mt][nt][c] = 0.f;

#pragma unroll 1
    for (int kc = 0; kc < 16; kc++) {
        if (kc < 15) { CP_WAIT1(); } else { CP_WAIT0(); }
        __syncthreads();

        const uint32_t* Wh = gs + (kc & 1) * 4 * GARR;
        const uint32_t* Wl = Wh + GARR;
        const uint32_t* Xh = Wh + 2 * GARR;
        const uint32_t* Xl = Wh + 3 * GARR;

#pragma unroll
        for (int ks = 0; ks < 2; ks++) {
            uint32_t Ah[4][4], Al[4][4];
#pragma unroll
            for (int mt = 0; mt < 4; mt++) {
                const int r0 = (wm + mt * 16 + g) * GW + ks * 8 + t;
                const int r1 = (wm + mt * 16 + 8 + g) * GW + ks * 8 + t;
                Ah[mt][0] = Wh[r0]; Ah[mt][1] = Wh[r1];
                Ah[mt][2] = Wh[r0 + 4]; Ah[mt][3] = Wh[r1 + 4];
                Al[mt][0] = Wl[r0]; Al[mt][1] = Wl[r1];
                Al[mt][2] = Wl[r0 + 4]; Al[mt][3] = Wl[r1 + 4];
            }
            uint32_t Bh[4][2], Bl[4][2];
#pragma unroll
            for (int nt = 0; nt < 4; nt++) {
                const int rr = (wn + nt * 8 + g) * GW + ks * 8 + t;
                Bh[nt][0] = Xh[rr]; Bh[nt][1] = Xh[rr + 4];
                Bl[nt][0] = Xl[rr]; Bl[nt][1] = Xl[rr + 4];
            }
#pragma unroll
            for (int mt = 0; mt < 4; mt++)
#pragma unroll
                for (int nt = 0; nt < 4; nt++) {
                    MMA_BF16(acc[mt][nt], Ah[mt], Bh[nt][0], Bh[nt][1]);
                    MMA_BF16(acc[mt][nt], Ah[mt], Bl[nt][0], Bl[nt][1]);
                    MMA_BF16(acc[mt][nt], Al[mt], Bh[nt][0], Bh[nt][1]);
                }
        }
        __syncthreads();

        if (kc + 2 < 16) {
            const uint32_t base = gsb + (kc & 1) * 4 * GARR * 4;
            const int kw4 = (kc + 2) * 4;
            for (int kk = tid; kk < 512; kk += 256) {
                const int r = kk >> 2, c = kk & 3;
                const uint32_t so = (uint32_t)(r * GW + c * 4) * 4;
                cpa16(base + so,                whb + (size_t)r * 64 + kw4 + c);
                cpa16(base + GARR * 4 + so,     wlb + (size_t)r * 64 + kw4 + c);
                cpa16(base + 2 * GARR * 4 + so, xhb + (size_t)r * 64 + kw4 + c);
                cpa16(base + 3 * GARR * 4 + so, xlb + (size_t)r * 64 + kw4 + c);
            }
            CP_COMMIT();
        }
    }

    if (mat == 2) {
        uint32_t* __restrict__ vh = (uint32_t*)g_vh;
        uint32_t* __restrict__ vl = (uint32_t*)g_vl;
        const size_t vbase = (size_t)b * CDIM * (NDIM / 2);
#pragma unroll
        for (int mt = 0; mt < 4; mt++) {
            const int o_a = o0 + wm + mt * 16 + g;
            const int o_b = o_a + 8;
            const float bia = bias[o_a];
            const float bib = bias[o_b];
#pragma unroll
            for (int nt = 0; nt < 4; nt++) {
                const int n = n0 + wn + nt * 8 + 2 * t;
                uint32_t h, l;
                splitbf(acc[mt][nt][0] + bia, acc[mt][nt][1] + bia, h, l);
                size_t wa = vbase + (size_t)o_a * (NDIM / 2) + (n >> 1);
                vh[wa] = h; vl[wa] = l;
                splitbf(acc[mt][nt][2] + bib, acc[mt][nt][3] + bib, h, l);
                wa = vbase + (size_t)o_b * (NDIM / 2) + (n >> 1);
                vh[wa] = h; vl[wa] = l;
            }
        }
    } else {
        float* __restrict__ Ep = (float*)gs;
#pragma unroll
        for (int mt = 0; mt < 4; mt++) {
            const int ol_a = wm + mt * 16 + g;
            const int ol_b = ol_a + 8;
            const int o_a = o0 + ol_a;
            const int o_b = o0 + ol_b;
            const float bia = bias[o_a];
            const float bib = bias[o_b];
            const int dda = o_a & 63;
            const int ddb = o_b & 63;
#pragma unroll
            for (int nt = 0; nt < 4; nt++) {
                const int nl = wn + nt * 8 + 2 * t;
                const int n  = n0 + nl;
                float v0 = acc[mt][nt][0] + bia;
                float v1 = acc[mt][nt][1] + bia;
                float v2 = acc[mt][nt][2] + bib;
                float v3 = acc[mt][nt][3] + bib;
                if (mat == 0) {
                    v0 *= QSCALE; v1 *= QSCALE; v2 *= QSCALE; v3 *= QSCALE;
                } else {
                    v0 += rel_h[dda * 32 + (n >> 5)] + rel_w[dda * 32 + (n & 31)];
                    v1 += rel_h[dda * 32 + ((n + 1) >> 5)] + rel_w[dda * 32 + ((n + 1) & 31)];
                    v2 += rel_h[ddb * 32 + (n >> 5)] + rel_w[ddb * 32 + (n & 31)];
                    v3 += rel_h[ddb * 32 + ((n + 1) >> 5)] + rel_w[ddb * 32 + ((n + 1) & 31)];
                }
                Ep[(nl + 0) * 132 + ol_a] = v0;
                Ep[(nl + 1) * 132 + ol_a] = v1;
                Ep[(nl + 0) * 132 + ol_b] = v2;
                Ep[(nl + 1) * 132 + ol_b] = v3;
            }
        }
        __syncthreads();

        uint2* __restrict__ dh = (uint2*)(mat ? g_kh : g_qh);
        uint2* __restrict__ dl = (uint2*)(mat ? g_kl : g_ql);
        const int h0 = o0 >> 6;
        for (int tt = tid; tt < 4096; tt += 256) {
            const int il   = tt >> 5;
            const int rem  = tt & 31;
            const int head = rem >> 4;
            const int wp   = rem & 15;
            const float4 f = *(const float4*)&Ep[il * 132 + head * 64 + 4 * wp];
            uint32_t hh0, ll0, hh1, ll1;
            splitbf(f.x, f.y, hh0, ll0);
            splitbf(f.z, f.w, hh1, ll1);
            const size_t di =
                ((size_t)(b * NHEADS + h0 + head) * NDIM + n0 + il) * 16 + wp;
            dh[di] = make_uint2(hh0, hh1);
            dl[di] = make_uint2(ll0, ll1);
        }
    }
}

// ---------------------------------------------------------------------------
// Kernel 2: flash attention. CHANGE: Q fragments loaded directly from gmem
// (no smem staging) -> CTA smem 92 KB -> 73.7 KB -> 3 CTAs/SM (12 warps).
// ---------------------------------------------------------------------------
#define ROWW 36
#define ARR  (64 * ROWW)
#define ATTN_SMEM_WORDS (8 * ARR)    // 18432 words = 73728 B

__global__ __launch_bounds__(128) void attn_mma_kernel(float* __restrict__ out)
{
    extern __shared__ uint32_t sw[];
    const uint32_t swb = (uint32_t)__cvta_generic_to_shared(sw);

    const int bh = blockIdx.y;
    const int i0 = blockIdx.x * 64;

    const int tid  = threadIdx.x;
    const int lane = tid & 31;
    const int warp = tid >> 5;
    const int g    = lane >> 2;
    const int t    = lane & 3;

    const uint4* khb = (const uint4*)(g_kh + (size_t)bh * NDIM * DHEAD);
    const uint4* klb = (const uint4*)(g_kl + (size_t)bh * NDIM * DHEAD);
    const uint4* vhb = (const uint4*)(g_vh + (size_t)bh * DHEAD * NDIM);
    const uint4* vlb = (const uint4*)(g_vl + (size_t)bh * DHEAD * NDIM);

    // issue K/V tiles 0 and 1 (buffers at swb + pb*4*ARR*4)
#pragma unroll
    for (int pb = 0; pb < 2; pb++) {
        const int j0 = pb * 64;
        const uint32_t base = swb + pb * 4 * ARR * 4;
        for (int kk = tid; kk < 512; kk += 128) {
            const int r = kk >> 3, c = kk & 7;
            const uint32_t so = (uint32_t)(r * ROWW + c * 4) * 4;
            cpa16(base + so,               khb + (size_t)(j0 + r) * 8 + c);
            cpa16(base + ARR * 4 + so,     klb + (size_t)(j0 + r) * 8 + c);
            cpa16(base + 2 * ARR * 4 + so, vhb + (size_t)r * 128 + (j0 >> 3) + c);
            cpa16(base + 3 * ARR * 4 + so, vlb + (size_t)r * 128 + (j0 >> 3) + c);
        }
        CP_COMMIT();
    }

    // Q fragments straight from gmem (one-time; rows are L2-hot from GEMM)
    uint32_t Ah[4][4], Al[4][4];
    {
        const uint32_t* qh0 =
            (const uint32_t*)(g_qh + ((size_t)bh * NDIM + i0 + warp * 16 + g) * DHEAD);
        const uint32_t* ql0 =
            (const uint32_t*)(g_ql + ((size_t)bh * NDIM + i0 + warp * 16 + g) * DHEAD);
        const uint32_t* qh1 = qh0 + 8 * 32;   // row +8 (32 words per row)
        const uint32_t* ql1 = ql0 + 8 * 32;
#pragma unroll
        for (int ks = 0; ks < 4; ks++) {
            Ah[ks][0] = qh0[8 * ks + t];
            Ah[ks][1] = qh1[8 * ks + t];
            Ah[ks][2] = qh0[8 * ks + t + 4];
            Ah[ks][3] = qh1[8 * ks + t + 4];
            Al[ks][0] = ql0[8 * ks + t];
            Al[ks][1] = ql1[8 * ks + t];
            Al[ks][2] = ql0[8 * ks + t + 4];
            Al[ks][3] = ql1[8 * ks + t + 4];
        }
    }

    float m0 = -INFINITY, m1 = -INFINITY, l0 = 0.f, l1 = 0.f;
    float O[8][4];
#pragma unroll
    for (int nt = 0; nt < 8; nt++)
#pragma unroll
        for (int c = 0; c < 4; c++) O[nt][c] = 0.f;

#pragma unroll 1
    for (int jt = 0; jt < NDIM / 64; jt++) {
        if (jt < NDIM / 64 - 1) { CP_WAIT1(); } else { CP_WAIT0(); }
        __syncthreads();

        const uint32_t* ksh = sw + (jt & 1) * 4 * ARR;
        const uint32_t* ksl = ksh + ARR;
        const uint32_t* vsh = ksh + 2 * ARR;
        const uint32_t* vsl = ksh + 3 * ARR;

        float S[8][4];
#pragma unroll
        for (int nt = 0; nt < 8; nt++)
#pragma unroll
            for (int c = 0; c < 4; c++) S[nt][c] = 0.f;

#pragma unroll
        for (int nt = 0; nt < 8; nt++) {
            const int kr = (8 * nt + g) * ROWW;
#pragma unroll
            for (int ks = 0; ks < 4; ks++) {
                const uint32_t b0h = ksh[kr + 8 * ks + t];
                const uint32_t b1h = ksh[kr + 8 * ks + t + 4];
                const uint32_t b0l = ksl[kr + 8 * ks + t];
                const uint32_t b1l = ksl[kr + 8 * ks + t + 4];
                MMA_BF16(S[nt], Ah[ks], b0h, b1h);
                MMA_BF16(S[nt], Ah[ks], b0l, b1l);
                MMA_BF16(S[nt], Al[ks], b0h, b1h);
            }
        }

        float mx0 = S[0][0], mx1 = S[0][2];
#pragma unroll
        for (int nt = 0; nt < 8; nt++) {
            mx0 = fmaxf(mx0, fmaxf(S[nt][0], S[nt][1]));
            mx1 = fmaxf(mx1, fmaxf(S[nt][2], S[nt][3]));
        }
        mx0 = fmaxf(mx0, __shfl_xor_sync(0xffffffffu, mx0, 1));
        mx0 = fmaxf(mx0, __shfl_xor_sync(0xffffffffu, mx0, 2));
        mx1 = fmaxf(mx1, __shfl_xor_sync(0xffffffffu, mx1, 1));
        mx1 = fmaxf(mx1, __shfl_xor_sync(0xffffffffu, mx1, 2));

        const float mn0 = fmaxf(m0, mx0);
        const float mn1 = fmaxf(m1, mx1);
        const float al0 = __expf(m0 - mn0);
        const float al1 = __expf(m1 - mn1);
        m0 = mn0; m1 = mn1;

        float rs0 = 0.f, rs1 = 0.f;
#pragma unroll
        for (int nt = 0; nt < 8; nt++) {
            S[nt][0] = __expf(S[nt][0] - mn0); rs0 += S[nt][0];
            S[nt][1] = __expf(S[nt][1] - mn0); rs0 += S[nt][1];
            S[nt][2] = __expf(S[nt][2] - mn1); rs1 += S[nt][2];
            S[nt][3] = __expf(S[nt][3] - mn1); rs1 += S[nt][3];
        }
        rs0 += __shfl_xor_sync(0xffffffffu, rs0, 1);
        rs0 += __shfl_xor_sync(0xffffffffu, rs0, 2);
        rs1 += __shfl_xor_sync(0xffffffffu, rs1, 1);
        rs1 += __shfl_xor_sync(0xffffffffu, rs1, 2);
        l0 = l0 * al0 + rs0;
        l1 = l1 * al1 + rs1;

#pragma unroll
        for (int nt = 0; nt < 8; nt++) {
            O[nt][0] *= al0; O[nt][1] *= al0;
            O[nt][2] *= al1; O[nt][3] *= al1;
        }

#pragma unroll
        for (int kk = 0; kk < 4; kk++) {
            uint32_t Ph[4], Pl[4];
            splitbf_trunc(S[2 * kk][0],     S[2 * kk][1],     Ph[0], Pl[0]);
            splitbf_trunc(S[2 * kk][2],     S[2 * kk][3],     Ph[1], Pl[1]);
            splitbf_trunc(S[2 * kk + 1][0], S[2 * kk + 1][1], Ph[2], Pl[2]);
            splitbf_trunc(S[2 * kk + 1][2], S[2 * kk + 1][3], Ph[3], Pl[3]);
#pragma unroll
            for (int nt = 0; nt < 8; nt++) {
                const int vr = (8 * nt + g) * ROWW;
                const uint32_t b0h = vsh[vr + 8 * kk + t];
                const uint32_t b1h = vsh[vr + 8 * kk + t + 4];
                const uint32_t b0l = vsl[vr + 8 * kk + t];
                const uint32_t b1l = vsl[vr + 8 * kk + t + 4];
                MMA_BF16(O[nt], Ph, b0h, b1h);
                MMA_BF16(O[nt], Ph, b0l, b1l);
                MMA_BF16(O[nt], Pl, b0h, b1h);
            }
        }
        __syncthreads();

        if (jt + 2 < NDIM / 64) {
            const int j0 = (jt + 2) * 64;
            const uint32_t base = swb + (jt & 1) * 4 * ARR * 4;
            for (int kk = tid; kk < 512; kk += 128) {
                const int r = kk >> 3, c = kk & 7;
                const uint32_t so = (uint32_t)(r * ROWW + c * 4) * 4;
                cpa16(base + so,               khb + (size_t)(j0 + r) * 8 + c);
                cpa16(base + ARR * 4 + so,     klb + (size_t)(j0 + r) * 8 + c);
                cpa16(base + 2 * ARR * 4 + so, vhb + (size_t)r * 128 + (j0 >> 3) + c);
                cpa16(base + 3 * ARR * 4 + so, vlb + (size_t)r * 128 + (j0 >> 3) + c);
            }
            CP_COMMIT();
        }
    }

    const float inv0 = 1.0f / l0;
    const float inv1 = 1.0f / l1;
    const int i = i0 + warp * 16 + g;
    float* __restrict__ op0 = out + ((size_t)bh * NDIM + i) * DHEAD;
    float* __restrict__ op1 = out + ((size_t)bh * NDIM + i + 8) * DHEAD;
#pragma unroll
    for (int nt = 0; nt < 8; nt++) {
        const int dd = 8 * nt + 2 * t;
        *(float2*)&op0[dd] = make_float2(O[nt][0] * inv0, O[nt][1] * inv0);
        *(float2*)&op1[dd] = make_float2(O[nt][2] * inv1, O[nt][3] * inv1);
    }
}

// ---------------------------------------------------------------------------
extern "C" void kernel_launch(void* const* d_in, const int* in_sizes, int n_in,
                              void* d_out, int out_size)
{
    const float* x     = (const float*)d_in[0];
    const float* Wq    = (const float*)d_in[1];
    const float* bq    = (const float*)d_in[2];
    const float* Wk    = (const float*)d_in[3];
    const float* bk    = (const float*)d_in[4];
    const float* Wv    = (const float*)d_in[5];
    const float* bv    = (const float*)d_in[6];
    const float* rel_h = (const float*)d_in[7];
    const float* rel_w = (const float*)d_in[8];
    float* out = (float*)d_out;

    cudaFuncSetAttribute(qkv_gemm_mma_kernel,
                         cudaFuncAttributeMaxDynamicSharedMemorySize,
                         GEMM_SMEM_WORDS * 4);
    cudaFuncSetAttribute(attn_mma_kernel,
                         cudaFuncAttributeMaxDynamicSharedMemorySize,
                         ATTN_SMEM_WORDS * 4);

    // 0) one-time operand splits
    conv_w_kernel<<<(3 * CDIM * CDIM / 4) / 256, 256>>>(Wq, Wk, Wv);
    dim3 gx(NDIM / 64, CDIM / 64, BDIM);
    conv_x_kernel<<<gx, 256>>>(x);

    // 1) QKV projections (q/k/v all emit split-bf16 directly)
    dim3 g1(NDIM / 128, CDIM / 128, 3 * BDIM);
    qkv_gemm_mma_kernel<<<g1, 256, GEMM_SMEM_WORDS * 4>>>(bq, bk, bv, rel_h, rel_w);

    // 2) tensor-core flash attention (3 CTAs/SM)
    dim3 g2(NDIM / 64, NBH);
    attn_mma_kernel<<<g2, 128, ATTN_SMEM_WORDS * 4>>>(out);
}